// round 1
// baseline (speedup 1.0000x reference)
#include <cuda_runtime.h>
#include <math.h>

#define B_   8
#define C_   256
#define H_   64
#define W_   64
#define T_   (B_*H_*W_)      // 32768 tokens
#define NH_  8
#define DH_  32
#define NR_  64
#define RSQ_ 64
#define TOPK_ 4

#define NEG_INF (__int_as_float(0xff800000))

// ---------------- scratch (static device memory; no allocation allowed) ----
__device__ float g_x1  [T_*C_];     // NHWC after pos-conv residual
__device__ float g_ln  [T_*C_];     // LN output / lepe+attn pre-projection (reused)
__device__ float g_qkv [T_*3*C_];   // qkv NHWC [T,768]; reused as MLP hidden [T,768]
__device__ float g_attn[T_*C_];     // attention out NHWC; reused as final y NHWC
__device__ float g_x2  [T_*C_];     // post-attention residual stream
__device__ float g_qr  [B_*NR_*C_];
__device__ float g_kr  [B_*NR_*C_];
__device__ int   g_idx [B_*NR_*TOPK_];

__device__ __forceinline__ float warp_sum(float v) {
#pragma unroll
    for (int o = 16; o > 0; o >>= 1) v += __shfl_xor_sync(0xffffffffu, v, o);
    return v;
}

// ---------------- 1. depthwise 3x3 pos conv + residual, NCHW -> NHWC -------
__global__ void posconv_kernel(const float* __restrict__ x,
                               const float* __restrict__ pw,
                               const float* __restrict__ pb,
                               float* __restrict__ out) {
    __shared__ float sm[32][33];
    int wb = blockIdx.x * 32, cb = blockIdx.y * 32;
    int bh = blockIdx.z;
    int b = bh >> 6, h = bh & 63;
    int tx = threadIdx.x, ty = threadIdx.y;
    for (int cs = ty; cs < 32; cs += 8) {
        int c = cb + cs;
        int w = wb + tx;
        const float* xp = x + ((size_t)(b * C_ + c)) * (H_ * W_);
        float acc = xp[h * W_ + w] + pb[c];
#pragma unroll
        for (int i = 0; i < 3; i++) {
            int hh = h + i - 1;
            if (hh < 0 || hh >= H_) continue;
#pragma unroll
            for (int j = 0; j < 3; j++) {
                int ww = w + j - 1;
                if (ww < 0 || ww >= W_) continue;
                acc += xp[hh * W_ + ww] * pw[c * 9 + i * 3 + j];
            }
        }
        sm[cs][tx] = acc;
    }
    __syncthreads();
    for (int ws = ty; ws < 32; ws += 8)
        out[((size_t)(b * H_ + h) * W_ + (wb + ws)) * C_ + cb + tx] = sm[tx][ws];
}

// ---------------- 2. LayerNorm over C (one warp per token) -----------------
__global__ void ln_kernel(const float* __restrict__ x,
                          const float* __restrict__ g,
                          const float* __restrict__ bta,
                          float* __restrict__ out) {
    int t = blockIdx.x * 8 + (threadIdx.x >> 5);
    int lane = threadIdx.x & 31;
    const float* row = x + (size_t)t * C_;
    float v[8];
    float s = 0.f;
#pragma unroll
    for (int k = 0; k < 8; k++) { v[k] = row[lane + k * 32]; s += v[k]; }
    s = warp_sum(s);
    float mu = s * (1.f / C_);
    float var = 0.f;
#pragma unroll
    for (int k = 0; k < 8; k++) { float d = v[k] - mu; var += d * d; }
    var = warp_sum(var);
    float rstd = rsqrtf(var * (1.f / C_) + 1e-6f);
    float* orow = out + (size_t)t * C_;
#pragma unroll
    for (int k = 0; k < 8; k++) {
        int c = lane + k * 32;
        orow[c] = (v[k] - mu) * rstd * g[c] + bta[c];
    }
}

// ---------------- 3. generic tiled SGEMM  out[t,o]=sum_k A[t,k]*W(k,o)+b ---
// W_OC: weight layout [N][K] (o-major, "oc");  else [K][N] ("co")
// EPI: 0 none, 1 exact gelu, 2 add residual
template <bool W_OC, int EPI>
__global__ void gemm_kernel(const float* __restrict__ A,
                            const float* __restrict__ Wt,
                            const float* __restrict__ bias,
                            const float* __restrict__ res,
                            float* __restrict__ out,
                            int M, int N, int K) {
    __shared__ float As[128][33];
    __shared__ float Bs[32][132];
    int tid = threadIdx.x;
    int tx = tid & 15, ty = tid >> 4;
    int bm = blockIdx.y * 128, bn = blockIdx.x * 128;
    float acc[8][8];
#pragma unroll
    for (int i = 0; i < 8; i++)
#pragma unroll
        for (int j = 0; j < 8; j++) acc[i][j] = 0.f;

    for (int k0 = 0; k0 < K; k0 += 32) {
#pragma unroll
        for (int i = 0; i < 16; i++) {
            int idx = tid + i * 256;
            int mm = idx >> 5, kk = idx & 31;
            As[mm][kk] = A[(size_t)(bm + mm) * K + k0 + kk];
        }
        if (W_OC) {
#pragma unroll
            for (int i = 0; i < 16; i++) {
                int idx = tid + i * 256;
                int nn = idx >> 5, kk = idx & 31;
                Bs[kk][nn] = Wt[(size_t)(bn + nn) * K + k0 + kk];
            }
        } else {
#pragma unroll
            for (int i = 0; i < 16; i++) {
                int idx = tid + i * 256;
                int kk = idx >> 7, nn = idx & 127;
                Bs[kk][nn] = Wt[(size_t)(k0 + kk) * N + bn + nn];
            }
        }
        __syncthreads();
#pragma unroll
        for (int kk = 0; kk < 32; kk++) {
            float a[8], bv[8];
#pragma unroll
            for (int i = 0; i < 8; i++) a[i] = As[ty * 8 + i][kk];
            float4 b0 = *(const float4*)&Bs[kk][tx * 8];
            float4 b1 = *(const float4*)&Bs[kk][tx * 8 + 4];
            bv[0] = b0.x; bv[1] = b0.y; bv[2] = b0.z; bv[3] = b0.w;
            bv[4] = b1.x; bv[5] = b1.y; bv[6] = b1.z; bv[7] = b1.w;
#pragma unroll
            for (int i = 0; i < 8; i++)
#pragma unroll
                for (int j = 0; j < 8; j++)
                    acc[i][j] = fmaf(a[i], bv[j], acc[i][j]);
        }
        __syncthreads();
    }
#pragma unroll
    for (int i = 0; i < 8; i++) {
        int row = bm + ty * 8 + i;
#pragma unroll
        for (int j = 0; j < 8; j++) {
            int col = bn + tx * 8 + j;
            float v = acc[i][j] + bias[col];
            if (EPI == 1) v = 0.5f * v * (1.f + erff(v * 0.70710678118654752f));
            if (EPI == 2) v += res[(size_t)row * N + col];
            out[(size_t)row * N + col] = v;
        }
    }
}

// ---------------- 4. region means of q,k (routing) -------------------------
__global__ void regmean_kernel(const float* __restrict__ qkv,
                               float* __restrict__ qr, float* __restrict__ kr) {
    int br = blockIdx.x;           // b*64 + r
    int b = br >> 6, r = br & 63;
    int c = threadIdx.x;
    int h0 = (r >> 3) << 3, w0 = (r & 7) << 3;
    float sq = 0.f, sk = 0.f;
#pragma unroll 4
    for (int p = 0; p < 64; p++) {
        int t = (b << 12) + (h0 + (p >> 3)) * W_ + w0 + (p & 7);
        sq += qkv[(size_t)t * 768 + c];
        sk += qkv[(size_t)t * 768 + 256 + c];
    }
    qr[(size_t)br * C_ + c] = sq * (1.f / 64.f);
    kr[(size_t)br * C_ + c] = sk * (1.f / 64.f);
}

// ---------------- 5. routing top-4 regions ---------------------------------
__global__ void route_topk_kernel(const float* __restrict__ qr,
                                  const float* __restrict__ kr,
                                  int* __restrict__ idxout) {
    int br = blockIdx.x;
    int b = br >> 6;
    __shared__ float qrow[256];
    __shared__ float sc[64];
    int tid = threadIdx.x;
    qrow[tid] = qr[(size_t)br * C_ + tid];
    __syncthreads();
    int wid = tid >> 5, lane = tid & 31;
#pragma unroll
    for (int jj = 0; jj < 8; jj++) {
        int j = wid * 8 + jj;
        const float* krow = kr + ((size_t)(b * 64 + j)) * C_;
        float d = 0.f;
#pragma unroll
        for (int k = 0; k < 8; k++) d += qrow[lane + k * 32] * krow[lane + k * 32];
        d = warp_sum(d);
        if (lane == 0) sc[j] = d;
    }
    __syncthreads();
    if (tid == 0) {
        for (int n = 0; n < TOPK_; n++) {
            float best = NEG_INF; int bi = 0;
            for (int j = 0; j < 64; j++)
                if (sc[j] > best) { best = sc[j]; bi = j; }
            sc[bi] = NEG_INF;
            idxout[br * TOPK_ + n] = bi;
        }
    }
}

// ---------------- 6. DSSA attention core -----------------------------------
// one CTA per (b, head, region); exact top-32-of-256 per query + softmax + AV
__global__ void attn_kernel(const float* __restrict__ qkv,
                            const int* __restrict__ ridx,
                            float* __restrict__ out) {
    extern __shared__ float smem[];
    float* Qs = smem;                  // 64 * 32
    float* Ks = smem + 2048;           // 256 * 33 (pad for conflict-free)
    float* Vs = smem + 2048 + 8448;    // 256 * 32
    int r = blockIdx.x, m = blockIdx.y, b = blockIdx.z;
    int tid = threadIdx.x;
    int rowq = tid >> 3, seg = tid & 7;
    int h0 = (r >> 3) << 3, w0 = (r & 7) << 3;
    const float SCALE = 0.0625f;       // 256^-0.5

#pragma unroll
    for (int pass = 0; pass < 2; pass++) {
        int p = pass * 32 + rowq;
        int t = (b << 12) + (h0 + (p >> 3)) * W_ + w0 + (p & 7);
        float4 q4 = *(const float4*)(qkv + (size_t)t * 768 + m * 32 + seg * 4);
        q4.x *= SCALE; q4.y *= SCALE; q4.z *= SCALE; q4.w *= SCALE;
        *(float4*)(Qs + p * 32 + seg * 4) = q4;
    }
    int regs_[4];
#pragma unroll
    for (int kk = 0; kk < 4; kk++) regs_[kk] = ridx[((b << 6) + r) * 4 + kk];
#pragma unroll
    for (int pass = 0; pass < 8; pass++) {
        int row = pass * 32 + rowq;
        int kk = row >> 6, p = row & 63;
        int rr = regs_[kk];
        int t = (b << 12) + (((rr >> 3) << 3) + (p >> 3)) * W_ + ((rr & 7) << 3) + (p & 7);
        float4 k4 = *(const float4*)(qkv + (size_t)t * 768 + 256 + m * 32 + seg * 4);
        float* kd = Ks + row * 33 + seg * 4;
        kd[0] = k4.x; kd[1] = k4.y; kd[2] = k4.z; kd[3] = k4.w;
        float4 v4 = *(const float4*)(qkv + (size_t)t * 768 + 512 + m * 32 + seg * 4);
        *(float4*)(Vs + row * 32 + seg * 4) = v4;
    }
    __syncthreads();

    int wid = tid >> 5, lane = tid & 31;
    int q0 = wid * 8;
    float s[8][8];
#pragma unroll
    for (int qi = 0; qi < 8; qi++)
#pragma unroll
        for (int ki = 0; ki < 8; ki++) s[qi][ki] = 0.f;

#pragma unroll 4
    for (int d = 0; d < 32; d++) {
        float kreg[8];
#pragma unroll
        for (int ki = 0; ki < 8; ki++) kreg[ki] = Ks[(ki * 32 + lane) * 33 + d];
#pragma unroll
        for (int qi = 0; qi < 8; qi++) {
            float qv = Qs[(q0 + qi) * 32 + d];
#pragma unroll
            for (int ki = 0; ki < 8; ki++)
                s[qi][ki] = fmaf(qv, kreg[ki], s[qi][ki]);
        }
    }

#pragma unroll
    for (int qi = 0; qi < 8; qi++) {
        float acc = 0.f, Z = 0.f, mval = 0.f;
#pragma unroll 1
        for (int it = 0; it < 32; it++) {
            float lv = s[qi][0]; int li = 0;
#pragma unroll
            for (int ki = 1; ki < 8; ki++)
                if (s[qi][ki] > lv) { lv = s[qi][ki]; li = ki; }
            int gi = li * 32 + lane;            // key index 0..255
#pragma unroll
            for (int off = 16; off > 0; off >>= 1) {
                float ov = __shfl_xor_sync(0xffffffffu, lv, off);
                int oi = __shfl_xor_sync(0xffffffffu, gi, off);
                if (ov > lv || (ov == lv && oi < gi)) { lv = ov; gi = oi; }
            }
            if (it == 0) mval = lv;
            float wgt = __expf(lv - mval);
            Z += wgt;
            acc = fmaf(wgt, Vs[gi * 32 + lane], acc);
            if ((gi & 31) == lane) {
                int slot = gi >> 5;
#pragma unroll
                for (int ki = 0; ki < 8; ki++)
                    if (ki == slot) s[qi][ki] = NEG_INF;
            }
        }
        int p = q0 + qi;
        int t = (b << 12) + (h0 + (p >> 3)) * W_ + w0 + (p & 7);
        out[(size_t)t * C_ + m * 32 + lane] = acc / Z;
    }
}

// ---------------- 7. LEPE 5x5 dwconv on v + add attention out --------------
__global__ void lepe_kernel(const float* __restrict__ attn,
                            const float* __restrict__ qkv,
                            const float* __restrict__ lw,
                            const float* __restrict__ lb,
                            float* __restrict__ out) {
    int bw = blockIdx.x;             // b*64 + w
    int b = bw >> 6, w = bw & 63;
    int c = threadIdx.x;
    float wt[25];
#pragma unroll
    for (int i = 0; i < 25; i++) wt[i] = lw[c * 25 + i];
    float bias = lb[c];
    float win[5][5];
#pragma unroll
    for (int i = 0; i < 5; i++)
#pragma unroll
        for (int j = 0; j < 5; j++) {
            int hh = i - 2, ww = w - 2 + j;
            win[i][j] = (hh < 0 || ww < 0 || ww >= W_) ? 0.f
                : qkv[((size_t)((b << 12) + hh * W_ + ww)) * 768 + 512 + c];
        }
#pragma unroll 1
    for (int h = 0; h < H_; h++) {
        size_t t = (size_t)(b << 12) + h * W_ + w;
        float acc = bias + attn[t * C_ + c];
#pragma unroll
        for (int i = 0; i < 5; i++)
#pragma unroll
            for (int j = 0; j < 5; j++) acc = fmaf(win[i][j], wt[i * 5 + j], acc);
        out[t * C_ + c] = acc;
        // slide window down one row
#pragma unroll
        for (int i = 0; i < 4; i++)
#pragma unroll
            for (int j = 0; j < 5; j++) win[i][j] = win[i + 1][j];
        int hh = h + 3;
#pragma unroll
        for (int j = 0; j < 5; j++) {
            int ww = w - 2 + j;
            win[4][j] = (hh >= H_ || ww < 0 || ww >= W_) ? 0.f
                : qkv[((size_t)((b << 12) + hh * W_ + ww)) * 768 + 512 + c];
        }
    }
}

// ---------------- 8. NHWC -> NCHW final transpose --------------------------
__global__ void nhwc2nchw_kernel(const float* __restrict__ in, float* __restrict__ out) {
    __shared__ float sm[32][33];
    int wb = blockIdx.x * 32, cb = blockIdx.y * 32;
    int bh = blockIdx.z;
    int b = bh >> 6, h = bh & 63;
    int tx = threadIdx.x, ty = threadIdx.y;
    for (int ws = ty; ws < 32; ws += 8)
        sm[tx][ws] = in[((size_t)(b * H_ + h) * W_ + wb + ws) * C_ + cb + tx];
    __syncthreads();
    for (int cs = ty; cs < 32; cs += 8)
        out[((size_t)(b * C_ + cb + cs) * H_ + h) * W_ + wb + tx] = sm[cs][tx];
}

// ---------------- launch ----------------------------------------------------
extern "C" void kernel_launch(void* const* d_in, const int* in_sizes, int n_in,
                              void* d_out, int out_size) {
    const float* x      = (const float*)d_in[0];
    const float* pos_w  = (const float*)d_in[1];
    const float* pos_b  = (const float*)d_in[2];
    const float* ln1_g  = (const float*)d_in[3];
    const float* ln1_b  = (const float*)d_in[4];
    const float* qkv_w  = (const float*)d_in[5];
    const float* qkv_b  = (const float*)d_in[6];
    const float* lepe_w = (const float*)d_in[7];
    const float* lepe_b = (const float*)d_in[8];
    const float* out_w  = (const float*)d_in[9];
    const float* out_b  = (const float*)d_in[10];
    const float* ln2_g  = (const float*)d_in[11];
    const float* ln2_b  = (const float*)d_in[12];
    const float* mlp_w1 = (const float*)d_in[13];
    const float* mlp_b1 = (const float*)d_in[14];
    const float* mlp_w2 = (const float*)d_in[15];
    const float* mlp_b2 = (const float*)d_in[16];

    float *x1, *ln, *qkv, *attn, *x2, *qr, *kr;
    int* idxp;
    cudaGetSymbolAddress((void**)&x1,   g_x1);
    cudaGetSymbolAddress((void**)&ln,   g_ln);
    cudaGetSymbolAddress((void**)&qkv,  g_qkv);
    cudaGetSymbolAddress((void**)&attn, g_attn);
    cudaGetSymbolAddress((void**)&x2,   g_x2);
    cudaGetSymbolAddress((void**)&qr,   g_qr);
    cudaGetSymbolAddress((void**)&kr,   g_kr);
    cudaGetSymbolAddress((void**)&idxp, g_idx);

    dim3 tb(32, 8);
    dim3 tg(W_ / 32, C_ / 32, B_ * H_);

    // 1. pos conv + residual (NCHW in -> NHWC x1)
    posconv_kernel<<<tg, tb>>>(x, pos_w, pos_b, x1);
    // 2. LN1
    ln_kernel<<<T_ / 8, 256>>>(x1, ln1_g, ln1_b, ln);
    // 3. qkv projection (W layout [O][C])
    gemm_kernel<true, 0><<<dim3(768 / 128, T_ / 128), 256>>>(ln, qkv_w, qkv_b, nullptr, qkv, T_, 768, 256);
    // 4-5. routing
    regmean_kernel<<<B_ * NR_, 256>>>(qkv, qr, kr);
    route_topk_kernel<<<B_ * NR_, 256>>>(qr, kr, idxp);
    // 6. attention
    int attn_smem = (64 * 32 + 256 * 33 + 256 * 32) * (int)sizeof(float);  // 74752 B
    cudaFuncSetAttribute(attn_kernel, cudaFuncAttributeMaxDynamicSharedMemorySize, attn_smem);
    attn_kernel<<<dim3(NR_, NH_, B_), 256, attn_smem>>>(qkv, idxp, attn);
    // 7. lepe dwconv(v) + attn  -> pre-projection buffer (reuse ln)
    lepe_kernel<<<B_ * W_, 256>>>(attn, qkv, lepe_w, lepe_b, ln);
    // 8. out projection + residual x1 -> x2
    gemm_kernel<true, 2><<<dim3(256 / 128, T_ / 128), 256>>>(ln, out_w, out_b, x1, x2, T_, 256, 256);
    // 9. LN2
    ln_kernel<<<T_ / 8, 256>>>(x2, ln2_g, ln2_b, ln);
    // 10. MLP fc1 + exact gelu (W layout [C][O]) -> hidden (reuse qkv buffer)
    gemm_kernel<false, 1><<<dim3(768 / 128, T_ / 128), 256>>>(ln, mlp_w1, mlp_b1, nullptr, qkv, T_, 768, 256);
    // 11. MLP fc2 + residual x2 -> y (reuse attn buffer)
    gemm_kernel<false, 2><<<dim3(256 / 128, T_ / 128), 256>>>(qkv, mlp_w2, mlp_b2, x2, attn, T_, 256, 768);
    // 12. NHWC -> NCHW
    nhwc2nchw_kernel<<<tg, tb>>>(attn, (float*)d_out);
}

// round 6
// speedup vs baseline: 1.3220x; 1.3220x over previous
#include <cuda_runtime.h>
#include <cuda_bf16.h>
#include <math.h>

#define B_   8
#define C_   256
#define H_   64
#define W_   64
#define T_   (B_*H_*W_)      // 32768 tokens
#define NH_  8
#define NR_  64
#define TOPK_ 4

#define NEG_INF (__int_as_float(0xff800000))

// ---------------- scratch (static device memory) ---------------------------
__device__ float g_x1  [T_*C_];         // NHWC after pos-conv residual
__device__ float g_qkv [T_*3*C_];       // qkv NHWC [T,768] fp32
__device__ float g_attn[T_*C_];         // attention out NHWC; reused as final y
__device__ float g_x2  [T_*C_];         // post-attention residual stream
__device__ float g_qr  [B_*NR_*C_];
__device__ float g_kr  [B_*NR_*C_];
__device__ int   g_idx [B_*NR_*TOPK_];
// split-bf16 activation buffers
__device__ __nv_bfloat16 g_ahi[T_*C_];      // LN1 / lepe / LN2 outputs
__device__ __nv_bfloat16 g_alo[T_*C_];
__device__ __nv_bfloat16 g_hhi[T_*3*C_];    // MLP hidden
__device__ __nv_bfloat16 g_hlo[T_*3*C_];
// split-bf16 weights, k-major [K][N]
__device__ __nv_bfloat16 g_wqkv_hi[C_*3*C_], g_wqkv_lo[C_*3*C_];
__device__ __nv_bfloat16 g_wout_hi[C_*C_],   g_wout_lo[C_*C_];
__device__ __nv_bfloat16 g_wm1_hi [C_*3*C_], g_wm1_lo [C_*3*C_];
__device__ __nv_bfloat16 g_wm2_hi [3*C_*C_], g_wm2_lo [3*C_*C_];

__device__ __forceinline__ float warp_sum(float v) {
#pragma unroll
    for (int o = 16; o > 0; o >>= 1) v += __shfl_xor_sync(0xffffffffu, v, o);
    return v;
}

__device__ __forceinline__ void split_bf16(float v, __nv_bfloat16& hi, __nv_bfloat16& lo) {
    hi = __float2bfloat16(v);
    lo = __float2bfloat16(v - __bfloat162float(hi));
}

// ---------------- 1. depthwise 3x3 pos conv + residual, NCHW -> NHWC -------
__global__ void posconv_kernel(const float* __restrict__ x,
                               const float* __restrict__ pw,
                               const float* __restrict__ pb,
                               float* __restrict__ out) {
    __shared__ float sm[32][33];
    int wb = blockIdx.x * 32, cb = blockIdx.y * 32;
    int bh = blockIdx.z;
    int b = bh >> 6, h = bh & 63;
    int tx = threadIdx.x, ty = threadIdx.y;
    for (int cs = ty; cs < 32; cs += 8) {
        int c = cb + cs;
        int w = wb + tx;
        const float* xp = x + ((size_t)(b * C_ + c)) * (H_ * W_);
        float acc = xp[h * W_ + w] + pb[c];
#pragma unroll
        for (int i = 0; i < 3; i++) {
            int hh = h + i - 1;
            if (hh < 0 || hh >= H_) continue;
#pragma unroll
            for (int j = 0; j < 3; j++) {
                int ww = w + j - 1;
                if (ww < 0 || ww >= W_) continue;
                acc += xp[hh * W_ + ww] * pw[c * 9 + i * 3 + j];
            }
        }
        sm[cs][tx] = acc;
    }
    __syncthreads();
    for (int ws = ty; ws < 32; ws += 8)
        out[((size_t)(b * H_ + h) * W_ + (wb + ws)) * C_ + cb + tx] = sm[tx][ws];
}

// ---------------- 2. LayerNorm over C -> split bf16 ------------------------
__global__ void ln_kernel(const float* __restrict__ x,
                          const float* __restrict__ g,
                          const float* __restrict__ bta,
                          __nv_bfloat16* __restrict__ ohi,
                          __nv_bfloat16* __restrict__ olo) {
    int t = blockIdx.x * 8 + (threadIdx.x >> 5);
    int lane = threadIdx.x & 31;
    const float* row = x + (size_t)t * C_;
    float v[8];
    float s = 0.f;
#pragma unroll
    for (int k = 0; k < 8; k++) { v[k] = row[lane + k * 32]; s += v[k]; }
    s = warp_sum(s);
    float mu = s * (1.f / C_);
    float var = 0.f;
#pragma unroll
    for (int k = 0; k < 8; k++) { float d = v[k] - mu; var += d * d; }
    var = warp_sum(var);
    float rstd = rsqrtf(var * (1.f / C_) + 1e-6f);
#pragma unroll
    for (int k = 0; k < 8; k++) {
        int c = lane + k * 32;
        float y = (v[k] - mu) * rstd * g[c] + bta[c];
        __nv_bfloat16 hi, lo; split_bf16(y, hi, lo);
        ohi[(size_t)t * C_ + c] = hi;
        olo[(size_t)t * C_ + c] = lo;
    }
}

// ---------------- weight conversion ----------------------------------------
// direct: W already [K][N]
__global__ void convw_kernel(const float* __restrict__ W,
                             __nv_bfloat16* __restrict__ hi,
                             __nv_bfloat16* __restrict__ lo, int total) {
    int i = blockIdx.x * 256 + threadIdx.x;
    if (i < total) { __nv_bfloat16 h, l; split_bf16(W[i], h, l); hi[i] = h; lo[i] = l; }
}
// transpose: W [N][K] -> out [K][N]
__global__ void convw_t_kernel(const float* __restrict__ W,
                               __nv_bfloat16* __restrict__ hi,
                               __nv_bfloat16* __restrict__ lo, int N, int K) {
    __shared__ float t[32][33];
    int kb = blockIdx.x * 32, nb = blockIdx.y * 32;
    int tx = threadIdx.x, ty = threadIdx.y;
    for (int i = ty; i < 32; i += 8)
        t[i][tx] = W[(size_t)(nb + i) * K + kb + tx];      // t[n_local][k_local]
    __syncthreads();
    for (int i = ty; i < 32; i += 8) {
        float v = t[tx][i];                                 // n_local=tx, k_local=i
        __nv_bfloat16 h, l; split_bf16(v, h, l);
        size_t o = (size_t)(kb + i) * N + nb + tx;
        hi[o] = h; lo[o] = l;
    }
}

// ---------------- split-bf16 tensor-core GEMM ------------------------------
// out[m,n] = sum_k A[m,k]*B[k,n] + bias[n]  (+epilogue)
// A given as (Ahi+Alo), B as (Bhi+Blo); 3-term bf16 mma reconstruction.
// EPI: 0 fp32 out; 1 exact gelu -> split bf16 out; 2 +res -> fp32 out
#define BKG 32
__device__ __forceinline__ void ldmA(unsigned* r, const __nv_bfloat16* p) {
    unsigned a = (unsigned)__cvta_generic_to_shared(p);
    asm volatile("ldmatrix.sync.aligned.m8n8.x4.shared.b16 {%0,%1,%2,%3},[%4];\n"
                 : "=r"(r[0]), "=r"(r[1]), "=r"(r[2]), "=r"(r[3]) : "r"(a));
}
__device__ __forceinline__ void ldmT(unsigned& r0, unsigned& r1, unsigned& r2, unsigned& r3,
                                     const __nv_bfloat16* p) {
    unsigned a = (unsigned)__cvta_generic_to_shared(p);
    asm volatile("ldmatrix.sync.aligned.m8n8.x4.trans.shared.b16 {%0,%1,%2,%3},[%4];\n"
                 : "=r"(r0), "=r"(r1), "=r"(r2), "=r"(r3) : "r"(a));
}
__device__ __forceinline__ void mma16816(float* d, const unsigned* a, const unsigned* b) {
    asm volatile(
        "mma.sync.aligned.m16n8k16.row.col.f32.bf16.bf16.f32 "
        "{%0,%1,%2,%3},{%4,%5,%6,%7},{%8,%9},{%0,%1,%2,%3};\n"
        : "+f"(d[0]), "+f"(d[1]), "+f"(d[2]), "+f"(d[3])
        : "r"(a[0]), "r"(a[1]), "r"(a[2]), "r"(a[3]), "r"(b[0]), "r"(b[1]));
}
__device__ __forceinline__ void cpa16(void* dst, const void* src) {
    unsigned d = (unsigned)__cvta_generic_to_shared(dst);
    asm volatile("cp.async.cg.shared.global [%0],[%1],16;\n" :: "r"(d), "l"(src));
}

template <int EPI>
__global__ void __launch_bounds__(256, 1)
mma_gemm_kernel(const __nv_bfloat16* __restrict__ Ahi,
                const __nv_bfloat16* __restrict__ Alo,
                const __nv_bfloat16* __restrict__ Bhi,
                const __nv_bfloat16* __restrict__ Blo,
                const float* __restrict__ bias,
                const float* __restrict__ res,
                float* __restrict__ outF,
                __nv_bfloat16* __restrict__ outHi,
                __nv_bfloat16* __restrict__ outLo,
                int M, int N, int K) {
    extern __shared__ __align__(16) char smraw[];
    __nv_bfloat16* sm = (__nv_bfloat16*)smraw;
    const int A_SZ = 128 * 40;   // padded stride 40
    const int B_SZ = 32 * 136;   // padded stride 136
    const int STAGE = 2 * A_SZ + 2 * B_SZ;
    int tid = threadIdx.x;
    int wid = tid >> 5, lane = tid & 31;
    int wm = (wid >> 1) * 32, wn = (wid & 1) * 64;
    int bm = blockIdx.y * 128, bn = blockIdx.x * 128;

    float acc[2][8][4];
#pragma unroll
    for (int i = 0; i < 2; i++)
#pragma unroll
        for (int j = 0; j < 8; j++)
#pragma unroll
            for (int q = 0; q < 4; q++) acc[i][j][q] = 0.f;

    auto load_stage = [&](int s, int k0) {
        __nv_bfloat16* As_h = sm + s * STAGE;
        __nv_bfloat16* As_l = As_h + A_SZ;
        __nv_bfloat16* Bs_h = As_l + A_SZ;
        __nv_bfloat16* Bs_l = Bs_h + B_SZ;
#pragma unroll
        for (int i = 0; i < 2; i++) {
            int ch = tid + i * 256;
            int r = ch >> 2, cs = (ch & 3) * 8;
            cpa16(As_h + r * 40 + cs, Ahi + (size_t)(bm + r) * K + k0 + cs);
            cpa16(As_l + r * 40 + cs, Alo + (size_t)(bm + r) * K + k0 + cs);
        }
#pragma unroll
        for (int i = 0; i < 2; i++) {
            int ch = tid + i * 256;
            int r = ch >> 4, cs = (ch & 15) * 8;
            cpa16(Bs_h + r * 136 + cs, Bhi + (size_t)(k0 + r) * N + bn + cs);
            cpa16(Bs_l + r * 136 + cs, Blo + (size_t)(k0 + r) * N + bn + cs);
        }
        asm volatile("cp.async.commit_group;\n");
    };

    int nk = K / BKG;
    load_stage(0, 0);
    for (int it = 0; it < nk; it++) {
        if (it + 1 < nk) {
            load_stage((it + 1) & 1, (it + 1) * BKG);
            asm volatile("cp.async.wait_group 1;\n");
        } else {
            asm volatile("cp.async.wait_group 0;\n");
        }
        __syncthreads();
        __nv_bfloat16* As_h = sm + (it & 1) * STAGE;
        __nv_bfloat16* As_l = As_h + A_SZ;
        __nv_bfloat16* Bs_h = As_l + A_SZ;
        __nv_bfloat16* Bs_l = Bs_h + B_SZ;
#pragma unroll
        for (int ks = 0; ks < 2; ks++) {
            int kb = ks * 16;
            unsigned ah[2][4], al[2][4];
            int ar = (lane & 7) + (lane & 8);
            int ac = kb + ((lane & 16) >> 1);
#pragma unroll
            for (int ti = 0; ti < 2; ti++) {
                ldmA(ah[ti], As_h + (wm + ti * 16 + ar) * 40 + ac);
                ldmA(al[ti], As_l + (wm + ti * 16 + ar) * 40 + ac);
            }
            unsigned bh[8][2], bl[8][2];
            int br = kb + (lane & 7) + ((lane & 16) >> 1);
            int bc = (lane & 8);
#pragma unroll
            for (int tj = 0; tj < 4; tj++) {
                unsigned t0, t1, t2, t3;
                ldmT(t0, t1, t2, t3, Bs_h + br * 136 + wn + tj * 16 + bc);
                bh[2 * tj][0] = t0; bh[2 * tj + 1][0] = t1;
                bh[2 * tj][1] = t2; bh[2 * tj + 1][1] = t3;
                ldmT(t0, t1, t2, t3, Bs_l + br * 136 + wn + tj * 16 + bc);
                bl[2 * tj][0] = t0; bl[2 * tj + 1][0] = t1;
                bl[2 * tj][1] = t2; bl[2 * tj + 1][1] = t3;
            }
#pragma unroll
            for (int ti = 0; ti < 2; ti++)
#pragma unroll
                for (int tj = 0; tj < 8; tj++) {
                    mma16816(acc[ti][tj], ah[ti], bh[tj]);
                    mma16816(acc[ti][tj], ah[ti], bl[tj]);
                    mma16816(acc[ti][tj], al[ti], bh[tj]);
                }
        }
        __syncthreads();
    }

    // epilogue
#pragma unroll
    for (int ti = 0; ti < 2; ti++) {
        int row0 = bm + wm + ti * 16 + (lane >> 2);
#pragma unroll
        for (int tj = 0; tj < 8; tj++) {
            int col = bn + wn + tj * 8 + (lane & 3) * 2;
            float b0 = bias[col], b1 = bias[col + 1];
#pragma unroll
            for (int half = 0; half < 2; half++) {
                int row = row0 + half * 8;
                float v0 = acc[ti][tj][half * 2 + 0] + b0;
                float v1 = acc[ti][tj][half * 2 + 1] + b1;
                size_t o = (size_t)row * N + col;
                if (EPI == 0) {
                    outF[o] = v0; outF[o + 1] = v1;
                } else if (EPI == 1) {
                    v0 = 0.5f * v0 * (1.f + erff(v0 * 0.70710678118654752f));
                    v1 = 0.5f * v1 * (1.f + erff(v1 * 0.70710678118654752f));
                    __nv_bfloat16 h0, l0, h1, l1;
                    split_bf16(v0, h0, l0); split_bf16(v1, h1, l1);
                    outHi[o] = h0; outHi[o + 1] = h1;
                    outLo[o] = l0; outLo[o + 1] = l1;
                } else {
                    v0 += res[o]; v1 += res[o + 1];
                    outF[o] = v0; outF[o + 1] = v1;
                }
            }
        }
    }
}

// ---------------- 4. region means of q,k (routing) -------------------------
__global__ void regmean_kernel(const float* __restrict__ qkv,
                               float* __restrict__ qr, float* __restrict__ kr) {
    int br = blockIdx.x;
    int b = br >> 6, r = br & 63;
    int c = threadIdx.x;
    int h0 = (r >> 3) << 3, w0 = (r & 7) << 3;
    float sq = 0.f, sk = 0.f;
#pragma unroll 4
    for (int p = 0; p < 64; p++) {
        int t = (b << 12) + (h0 + (p >> 3)) * W_ + w0 + (p & 7);
        sq += qkv[(size_t)t * 768 + c];
        sk += qkv[(size_t)t * 768 + 256 + c];
    }
    qr[(size_t)br * C_ + c] = sq * (1.f / 64.f);
    kr[(size_t)br * C_ + c] = sk * (1.f / 64.f);
}

// ---------------- 5. routing top-4 regions ---------------------------------
__global__ void route_topk_kernel(const float* __restrict__ qr,
                                  const float* __restrict__ kr,
                                  int* __restrict__ idxout) {
    int br = blockIdx.x;
    int b = br >> 6;
    __shared__ float qrow[256];
    __shared__ float sc[64];
    int tid = threadIdx.x;
    qrow[tid] = qr[(size_t)br * C_ + tid];
    __syncthreads();
    int wid = tid >> 5, lane = tid & 31;
#pragma unroll
    for (int jj = 0; jj < 8; jj++) {
        int j = wid * 8 + jj;
        const float* krow = kr + ((size_t)(b * 64 + j)) * C_;
        float d = 0.f;
#pragma unroll
        for (int k = 0; k < 8; k++) d += qrow[lane + k * 32] * krow[lane + k * 32];
        d = warp_sum(d);
        if (lane == 0) sc[j] = d;
    }
    __syncthreads();
    if (tid == 0) {
        for (int n = 0; n < TOPK_; n++) {
            float best = NEG_INF; int bi = 0;
            for (int j = 0; j < 64; j++)
                if (sc[j] > best) { best = sc[j]; bi = j; }
            sc[bi] = NEG_INF;
            idxout[br * TOPK_ + n] = bi;
        }
    }
}

// ---------------- 6. DSSA attention core -----------------------------------
__global__ void attn_kernel(const float* __restrict__ qkv,
                            const int* __restrict__ ridx,
                            float* __restrict__ out) {
    extern __shared__ float smem[];
    float* Qs = smem;                  // 64 * 32
    float* Ks = smem + 2048;           // 256 * 33
    float* Vs = smem + 2048 + 8448;    // 256 * 32
    int r = blockIdx.x, m = blockIdx.y, b = blockIdx.z;
    int tid = threadIdx.x;
    int rowq = tid >> 3, seg = tid & 7;
    int h0 = (r >> 3) << 3, w0 = (r & 7) << 3;
    const float SCALE = 0.0625f;

#pragma unroll
    for (int pass = 0; pass < 2; pass++) {
        int p = pass * 32 + rowq;
        int t = (b << 12) + (h0 + (p >> 3)) * W_ + w0 + (p & 7);
        float4 q4 = *(const float4*)(qkv + (size_t)t * 768 + m * 32 + seg * 4);
        q4.x *= SCALE; q4.y *= SCALE; q4.z *= SCALE; q4.w *= SCALE;
        *(float4*)(Qs + p * 32 + seg * 4) = q4;
    }
    int regs_[4];
#pragma unroll
    for (int kk = 0; kk < 4; kk++) regs_[kk] = ridx[((b << 6) + r) * 4 + kk];
#pragma unroll
    for (int pass = 0; pass < 8; pass++) {
        int row = pass * 32 + rowq;
        int kk = row >> 6, p = row & 63;
        int rr = regs_[kk];
        int t = (b << 12) + (((rr >> 3) << 3) + (p >> 3)) * W_ + ((rr & 7) << 3) + (p & 7);
        float4 k4 = *(const float4*)(qkv + (size_t)t * 768 + 256 + m * 32 + seg * 4);
        float* kd = Ks + row * 33 + seg * 4;
        kd[0] = k4.x; kd[1] = k4.y; kd[2] = k4.z; kd[3] = k4.w;
        float4 v4 = *(const float4*)(qkv + (size_t)t * 768 + 512 + m * 32 + seg * 4);
        *(float4*)(Vs + row * 32 + seg * 4) = v4;
    }
    __syncthreads();

    int wid = tid >> 5, lane = tid & 31;
    int q0 = wid * 8;
    float s[8][8];
#pragma unroll
    for (int qi = 0; qi < 8; qi++)
#pragma unroll
        for (int ki = 0; ki < 8; ki++) s[qi][ki] = 0.f;

#pragma unroll 4
    for (int d = 0; d < 32; d++) {
        float kreg[8];
#pragma unroll
        for (int ki = 0; ki < 8; ki++) kreg[ki] = Ks[(ki * 32 + lane) * 33 + d];
#pragma unroll
        for (int qi = 0; qi < 8; qi++) {
            float qv = Qs[(q0 + qi) * 32 + d];
#pragma unroll
            for (int ki = 0; ki < 8; ki++)
                s[qi][ki] = fmaf(qv, kreg[ki], s[qi][ki]);
        }
    }

#pragma unroll
    for (int qi = 0; qi < 8; qi++) {
        float acc = 0.f, Z = 0.f, mval = 0.f;
#pragma unroll 1
        for (int it = 0; it < 32; it++) {
            float lv = s[qi][0]; int li = 0;
#pragma unroll
            for (int ki = 1; ki < 8; ki++)
                if (s[qi][ki] > lv) { lv = s[qi][ki]; li = ki; }
            int gi = li * 32 + lane;
#pragma unroll
            for (int off = 16; off > 0; off >>= 1) {
                float ov = __shfl_xor_sync(0xffffffffu, lv, off);
                int oi = __shfl_xor_sync(0xffffffffu, gi, off);
                if (ov > lv || (ov == lv && oi < gi)) { lv = ov; gi = oi; }
            }
            if (it == 0) mval = lv;
            float wgt = __expf(lv - mval);
            Z += wgt;
            acc = fmaf(wgt, Vs[gi * 32 + lane], acc);
            if ((gi & 31) == lane) {
                int slot = gi >> 5;
#pragma unroll
                for (int ki = 0; ki < 8; ki++)
                    if (ki == slot) s[qi][ki] = NEG_INF;
            }
        }
        int p = q0 + qi;
        int t = (b << 12) + (h0 + (p >> 3)) * W_ + w0 + (p & 7);
        out[(size_t)t * C_ + m * 32 + lane] = acc / Z;
    }
}

// ---------------- 7. LEPE 5x5 dwconv on v + attn -> split bf16 -------------
__global__ void lepe_kernel(const float* __restrict__ attn,
                            const float* __restrict__ qkv,
                            const float* __restrict__ lw,
                            const float* __restrict__ lb,
                            __nv_bfloat16* __restrict__ ohi,
                            __nv_bfloat16* __restrict__ olo) {
    int bw = blockIdx.x;
    int b = bw >> 6, w = bw & 63;
    int c = threadIdx.x;
    float wt[25];
#pragma unroll
    for (int i = 0; i < 25; i++) wt[i] = lw[c * 25 + i];
    float bias = lb[c];
    float win[5][5];
#pragma unroll
    for (int i = 0; i < 5; i++)
#pragma unroll
        for (int j = 0; j < 5; j++) {
            int hh = i - 2, ww = w - 2 + j;
            win[i][j] = (hh < 0 || ww < 0 || ww >= W_) ? 0.f
                : qkv[((size_t)((b << 12) + hh * W_ + ww)) * 768 + 512 + c];
        }
#pragma unroll 1
    for (int h = 0; h < H_; h++) {
        size_t t = (size_t)(b << 12) + h * W_ + w;
        float acc = bias + attn[t * C_ + c];
#pragma unroll
        for (int i = 0; i < 5; i++)
#pragma unroll
            for (int j = 0; j < 5; j++) acc = fmaf(win[i][j], wt[i * 5 + j], acc);
        __nv_bfloat16 hi, lo; split_bf16(acc, hi, lo);
        ohi[t * C_ + c] = hi;
        olo[t * C_ + c] = lo;
#pragma unroll
        for (int i = 0; i < 4; i++)
#pragma unroll
            for (int j = 0; j < 5; j++) win[i][j] = win[i + 1][j];
        int hh = h + 3;
#pragma unroll
        for (int j = 0; j < 5; j++) {
            int ww = w - 2 + j;
            win[4][j] = (hh >= H_ || ww < 0 || ww >= W_) ? 0.f
                : qkv[((size_t)((b << 12) + hh * W_ + ww)) * 768 + 512 + c];
        }
    }
}

// ---------------- 8. NHWC -> NCHW final transpose --------------------------
__global__ void nhwc2nchw_kernel(const float* __restrict__ in, float* __restrict__ out) {
    __shared__ float sm[32][33];
    int wb = blockIdx.x * 32, cb = blockIdx.y * 32;
    int bh = blockIdx.z;
    int b = bh >> 6, h = bh & 63;
    int tx = threadIdx.x, ty = threadIdx.y;
    for (int ws = ty; ws < 32; ws += 8)
        sm[tx][ws] = in[((size_t)(b * H_ + h) * W_ + wb + ws) * C_ + cb + tx];
    __syncthreads();
    for (int cs = ty; cs < 32; cs += 8)
        out[((size_t)(b * C_ + cb + cs) * H_ + h) * W_ + wb + tx] = sm[cs][tx];
}

// ---------------- launch ----------------------------------------------------
extern "C" void kernel_launch(void* const* d_in, const int* in_sizes, int n_in,
                              void* d_out, int out_size) {
    const float* x      = (const float*)d_in[0];
    const float* pos_w  = (const float*)d_in[1];
    const float* pos_b  = (const float*)d_in[2];
    const float* ln1_g  = (const float*)d_in[3];
    const float* ln1_b  = (const float*)d_in[4];
    const float* qkv_w  = (const float*)d_in[5];
    const float* qkv_b  = (const float*)d_in[6];
    const float* lepe_w = (const float*)d_in[7];
    const float* lepe_b = (const float*)d_in[8];
    const float* out_w  = (const float*)d_in[9];
    const float* out_b  = (const float*)d_in[10];
    const float* ln2_g  = (const float*)d_in[11];
    const float* ln2_b  = (const float*)d_in[12];
    const float* mlp_w1 = (const float*)d_in[13];
    const float* mlp_b1 = (const float*)d_in[14];
    const float* mlp_w2 = (const float*)d_in[15];
    const float* mlp_b2 = (const float*)d_in[16];

    float *x1, *qkv, *attn, *x2, *qr, *kr;
    int* idxp;
    __nv_bfloat16 *ahi, *alo, *hhi, *hlo;
    __nv_bfloat16 *wqh, *wql, *woh, *wol, *w1h, *w1l, *w2h, *w2l;
    cudaGetSymbolAddress((void**)&x1,   g_x1);
    cudaGetSymbolAddress((void**)&qkv,  g_qkv);
    cudaGetSymbolAddress((void**)&attn, g_attn);
    cudaGetSymbolAddress((void**)&x2,   g_x2);
    cudaGetSymbolAddress((void**)&qr,   g_qr);
    cudaGetSymbolAddress((void**)&kr,   g_kr);
    cudaGetSymbolAddress((void**)&idxp, g_idx);
    cudaGetSymbolAddress((void**)&ahi,  g_ahi);
    cudaGetSymbolAddress((void**)&alo,  g_alo);
    cudaGetSymbolAddress((void**)&hhi,  g_hhi);
    cudaGetSymbolAddress((void**)&hlo,  g_hlo);
    cudaGetSymbolAddress((void**)&wqh,  g_wqkv_hi);
    cudaGetSymbolAddress((void**)&wql,  g_wqkv_lo);
    cudaGetSymbolAddress((void**)&woh,  g_wout_hi);
    cudaGetSymbolAddress((void**)&wol,  g_wout_lo);
    cudaGetSymbolAddress((void**)&w1h,  g_wm1_hi);
    cudaGetSymbolAddress((void**)&w1l,  g_wm1_lo);
    cudaGetSymbolAddress((void**)&w2h,  g_wm2_hi);
    cudaGetSymbolAddress((void**)&w2l,  g_wm2_lo);

    int gemm_smem = (2 * (2 * 128 * 40 + 2 * 32 * 136)) * 2;   // 75776 B
    cudaFuncSetAttribute(mma_gemm_kernel<0>, cudaFuncAttributeMaxDynamicSharedMemorySize, gemm_smem);
    cudaFuncSetAttribute(mma_gemm_kernel<1>, cudaFuncAttributeMaxDynamicSharedMemorySize, gemm_smem);
    cudaFuncSetAttribute(mma_gemm_kernel<2>, cudaFuncAttributeMaxDynamicSharedMemorySize, gemm_smem);

    dim3 tb(32, 8);
    dim3 tg(W_ / 32, C_ / 32, B_ * H_);

    // weight conversion (cheap, every launch)
    convw_t_kernel<<<dim3(C_ / 32, 3 * C_ / 32), tb>>>(qkv_w, wqh, wql, 3 * C_, C_);
    convw_t_kernel<<<dim3(C_ / 32, C_ / 32),     tb>>>(out_w, woh, wol, C_, C_);
    convw_kernel<<<(C_ * 3 * C_) / 256, 256>>>(mlp_w1, w1h, w1l, C_ * 3 * C_);
    convw_kernel<<<(3 * C_ * C_) / 256, 256>>>(mlp_w2, w2h, w2l, 3 * C_ * C_);

    // 1. pos conv + residual (NCHW -> NHWC)
    posconv_kernel<<<tg, tb>>>(x, pos_w, pos_b, x1);
    // 2. LN1 -> split bf16
    ln_kernel<<<T_ / 8, 256>>>(x1, ln1_g, ln1_b, ahi, alo);
    // 3. qkv projection -> fp32
    mma_gemm_kernel<0><<<dim3(768 / 128, T_ / 128), 256, gemm_smem>>>(
        ahi, alo, wqh, wql, qkv_b, nullptr, qkv, nullptr, nullptr, T_, 768, 256);
    // 4-5. routing
    regmean_kernel<<<B_ * NR_, 256>>>(qkv, qr, kr);
    route_topk_kernel<<<B_ * NR_, 256>>>(qr, kr, idxp);
    // 6. attention
    int attn_smem = (64 * 32 + 256 * 33 + 256 * 32) * (int)sizeof(float);
    cudaFuncSetAttribute(attn_kernel, cudaFuncAttributeMaxDynamicSharedMemorySize, attn_smem);
    attn_kernel<<<dim3(NR_, NH_, B_), 256, attn_smem>>>(qkv, idxp, attn);
    // 7. lepe(v) + attn -> split bf16
    lepe_kernel<<<B_ * W_, 256>>>(attn, qkv, lepe_w, lepe_b, ahi, alo);
    // 8. out projection + residual -> x2
    mma_gemm_kernel<2><<<dim3(256 / 128, T_ / 128), 256, gemm_smem>>>(
        ahi, alo, woh, wol, out_b, x1, x2, nullptr, nullptr, T_, 256, 256);
    // 9. LN2 -> split bf16
    ln_kernel<<<T_ / 8, 256>>>(x2, ln2_g, ln2_b, ahi, alo);
    // 10. MLP fc1 + gelu -> split bf16 hidden
    mma_gemm_kernel<1><<<dim3(768 / 128, T_ / 128), 256, gemm_smem>>>(
        ahi, alo, w1h, w1l, mlp_b1, nullptr, nullptr, hhi, hlo, T_, 768, 256);
    // 11. MLP fc2 + residual -> y (reuse attn buffer)
    mma_gemm_kernel<2><<<dim3(256 / 128, T_ / 128), 256, gemm_smem>>>(
        hhi, hlo, w2h, w2l, mlp_b2, x2, attn, nullptr, nullptr, T_, 256, 768);
    // 12. NHWC -> NCHW
    nhwc2nchw_kernel<<<tg, tb>>>(attn, (float*)d_out);
}

// round 7
// speedup vs baseline: 2.0275x; 1.5336x over previous
#include <cuda_runtime.h>
#include <cuda_bf16.h>
#include <math.h>

#define B_   8
#define C_   256
#define H_   64
#define W_   64
#define T_   (B_*H_*W_)      // 32768 tokens
#define NH_  8
#define NR_  64
#define TOPK_ 4

#define NEG_INF (__int_as_float(0xff800000))

// ---------------- scratch (static device memory) ---------------------------
__device__ float g_x1  [T_*C_];         // NHWC after pos-conv residual
__device__ float g_qkv [T_*3*C_];       // qkv NHWC [T,768] fp32
__device__ float g_attn[T_*C_];         // attention out NHWC; reused as final y
__device__ float g_x2  [T_*C_];         // post-attention residual stream
__device__ float g_qr  [B_*NR_*C_];
__device__ float g_kr  [B_*NR_*C_];
__device__ int   g_idx [B_*NR_*TOPK_];
// split-bf16 activation buffers
__device__ __nv_bfloat16 g_ahi[T_*C_];      // LN1 / lepe / LN2 outputs
__device__ __nv_bfloat16 g_alo[T_*C_];
__device__ __nv_bfloat16 g_hhi[T_*3*C_];    // MLP hidden
__device__ __nv_bfloat16 g_hlo[T_*3*C_];
// split-bf16 weights, k-major [K][N]
__device__ __nv_bfloat16 g_wqkv_hi[C_*3*C_], g_wqkv_lo[C_*3*C_];
__device__ __nv_bfloat16 g_wout_hi[C_*C_],   g_wout_lo[C_*C_];
__device__ __nv_bfloat16 g_wm1_hi [C_*3*C_], g_wm1_lo [C_*3*C_];
__device__ __nv_bfloat16 g_wm2_hi [3*C_*C_], g_wm2_lo [3*C_*C_];

__device__ __forceinline__ float warp_sum(float v) {
#pragma unroll
    for (int o = 16; o > 0; o >>= 1) v += __shfl_xor_sync(0xffffffffu, v, o);
    return v;
}

__device__ __forceinline__ void split_bf16(float v, __nv_bfloat16& hi, __nv_bfloat16& lo) {
    hi = __float2bfloat16(v);
    lo = __float2bfloat16(v - __bfloat162float(hi));
}

// order-preserving float<->uint transforms
__device__ __forceinline__ unsigned f2u(float f) {
    unsigned b = __float_as_uint(f);
    return ((int)b < 0) ? ~b : (b | 0x80000000u);
}
__device__ __forceinline__ float u2f(unsigned u) {
    unsigned b = (u & 0x80000000u) ? (u & 0x7fffffffu) : ~u;
    return __uint_as_float(b);
}

// ---------------- 1. depthwise 3x3 pos conv + residual, NCHW -> NHWC -------
__global__ void posconv_kernel(const float* __restrict__ x,
                               const float* __restrict__ pw,
                               const float* __restrict__ pb,
                               float* __restrict__ out) {
    __shared__ float sm[32][33];
    int wb = blockIdx.x * 32, cb = blockIdx.y * 32;
    int bh = blockIdx.z;
    int b = bh >> 6, h = bh & 63;
    int tx = threadIdx.x, ty = threadIdx.y;
    for (int cs = ty; cs < 32; cs += 8) {
        int c = cb + cs;
        int w = wb + tx;
        const float* xp = x + ((size_t)(b * C_ + c)) * (H_ * W_);
        float acc = xp[h * W_ + w] + pb[c];
#pragma unroll
        for (int i = 0; i < 3; i++) {
            int hh = h + i - 1;
            if (hh < 0 || hh >= H_) continue;
#pragma unroll
            for (int j = 0; j < 3; j++) {
                int ww = w + j - 1;
                if (ww < 0 || ww >= W_) continue;
                acc += xp[hh * W_ + ww] * pw[c * 9 + i * 3 + j];
            }
        }
        sm[cs][tx] = acc;
    }
    __syncthreads();
    for (int ws = ty; ws < 32; ws += 8)
        out[((size_t)(b * H_ + h) * W_ + (wb + ws)) * C_ + cb + tx] = sm[tx][ws];
}

// ---------------- 2. LayerNorm over C -> split bf16 ------------------------
__global__ void ln_kernel(const float* __restrict__ x,
                          const float* __restrict__ g,
                          const float* __restrict__ bta,
                          __nv_bfloat16* __restrict__ ohi,
                          __nv_bfloat16* __restrict__ olo) {
    int t = blockIdx.x * 8 + (threadIdx.x >> 5);
    int lane = threadIdx.x & 31;
    const float* row = x + (size_t)t * C_;
    float v[8];
    float s = 0.f;
#pragma unroll
    for (int k = 0; k < 8; k++) { v[k] = row[lane + k * 32]; s += v[k]; }
    s = warp_sum(s);
    float mu = s * (1.f / C_);
    float var = 0.f;
#pragma unroll
    for (int k = 0; k < 8; k++) { float d = v[k] - mu; var += d * d; }
    var = warp_sum(var);
    float rstd = rsqrtf(var * (1.f / C_) + 1e-6f);
#pragma unroll
    for (int k = 0; k < 8; k++) {
        int c = lane + k * 32;
        float y = (v[k] - mu) * rstd * g[c] + bta[c];
        __nv_bfloat16 hi, lo; split_bf16(y, hi, lo);
        ohi[(size_t)t * C_ + c] = hi;
        olo[(size_t)t * C_ + c] = lo;
    }
}

// ---------------- weight conversion ----------------------------------------
__global__ void convw_kernel(const float* __restrict__ W,
                             __nv_bfloat16* __restrict__ hi,
                             __nv_bfloat16* __restrict__ lo, int total) {
    int i = blockIdx.x * 256 + threadIdx.x;
    if (i < total) { __nv_bfloat16 h, l; split_bf16(W[i], h, l); hi[i] = h; lo[i] = l; }
}
__global__ void convw_t_kernel(const float* __restrict__ W,
                               __nv_bfloat16* __restrict__ hi,
                               __nv_bfloat16* __restrict__ lo, int N, int K) {
    __shared__ float t[32][33];
    int kb = blockIdx.x * 32, nb = blockIdx.y * 32;
    int tx = threadIdx.x, ty = threadIdx.y;
    for (int i = ty; i < 32; i += 8)
        t[i][tx] = W[(size_t)(nb + i) * K + kb + tx];
    __syncthreads();
    for (int i = ty; i < 32; i += 8) {
        float v = t[tx][i];
        __nv_bfloat16 h, l; split_bf16(v, h, l);
        size_t o = (size_t)(kb + i) * N + nb + tx;
        hi[o] = h; lo[o] = l;
    }
}

// ---------------- split-bf16 tensor-core GEMM ------------------------------
#define BKG 32
__device__ __forceinline__ void ldmA(unsigned* r, const __nv_bfloat16* p) {
    unsigned a = (unsigned)__cvta_generic_to_shared(p);
    asm volatile("ldmatrix.sync.aligned.m8n8.x4.shared.b16 {%0,%1,%2,%3},[%4];\n"
                 : "=r"(r[0]), "=r"(r[1]), "=r"(r[2]), "=r"(r[3]) : "r"(a));
}
__device__ __forceinline__ void ldmT(unsigned& r0, unsigned& r1, unsigned& r2, unsigned& r3,
                                     const __nv_bfloat16* p) {
    unsigned a = (unsigned)__cvta_generic_to_shared(p);
    asm volatile("ldmatrix.sync.aligned.m8n8.x4.trans.shared.b16 {%0,%1,%2,%3},[%4];\n"
                 : "=r"(r0), "=r"(r1), "=r"(r2), "=r"(r3) : "r"(a));
}
__device__ __forceinline__ void mma16816(float* d, const unsigned* a, const unsigned* b) {
    asm volatile(
        "mma.sync.aligned.m16n8k16.row.col.f32.bf16.bf16.f32 "
        "{%0,%1,%2,%3},{%4,%5,%6,%7},{%8,%9},{%0,%1,%2,%3};\n"
        : "+f"(d[0]), "+f"(d[1]), "+f"(d[2]), "+f"(d[3])
        : "r"(a[0]), "r"(a[1]), "r"(a[2]), "r"(a[3]), "r"(b[0]), "r"(b[1]));
}
__device__ __forceinline__ void cpa16(void* dst, const void* src) {
    unsigned d = (unsigned)__cvta_generic_to_shared(dst);
    asm volatile("cp.async.cg.shared.global [%0],[%1],16;\n" :: "r"(d), "l"(src));
}

template <int EPI>
__global__ void __launch_bounds__(256, 1)
mma_gemm_kernel(const __nv_bfloat16* __restrict__ Ahi,
                const __nv_bfloat16* __restrict__ Alo,
                const __nv_bfloat16* __restrict__ Bhi,
                const __nv_bfloat16* __restrict__ Blo,
                const float* __restrict__ bias,
                const float* __restrict__ res,
                float* __restrict__ outF,
                __nv_bfloat16* __restrict__ outHi,
                __nv_bfloat16* __restrict__ outLo,
                int M, int N, int K) {
    extern __shared__ __align__(16) char smraw[];
    __nv_bfloat16* sm = (__nv_bfloat16*)smraw;
    const int A_SZ = 128 * 40;
    const int B_SZ = 32 * 136;
    const int STAGE = 2 * A_SZ + 2 * B_SZ;
    int tid = threadIdx.x;
    int wid = tid >> 5, lane = tid & 31;
    int wm = (wid >> 1) * 32, wn = (wid & 1) * 64;
    int bm = blockIdx.y * 128, bn = blockIdx.x * 128;

    float acc[2][8][4];
#pragma unroll
    for (int i = 0; i < 2; i++)
#pragma unroll
        for (int j = 0; j < 8; j++)
#pragma unroll
            for (int q = 0; q < 4; q++) acc[i][j][q] = 0.f;

    auto load_stage = [&](int s, int k0) {
        __nv_bfloat16* As_h = sm + s * STAGE;
        __nv_bfloat16* As_l = As_h + A_SZ;
        __nv_bfloat16* Bs_h = As_l + A_SZ;
        __nv_bfloat16* Bs_l = Bs_h + B_SZ;
#pragma unroll
        for (int i = 0; i < 2; i++) {
            int ch = tid + i * 256;
            int r = ch >> 2, cs = (ch & 3) * 8;
            cpa16(As_h + r * 40 + cs, Ahi + (size_t)(bm + r) * K + k0 + cs);
            cpa16(As_l + r * 40 + cs, Alo + (size_t)(bm + r) * K + k0 + cs);
        }
#pragma unroll
        for (int i = 0; i < 2; i++) {
            int ch = tid + i * 256;
            int r = ch >> 4, cs = (ch & 15) * 8;
            cpa16(Bs_h + r * 136 + cs, Bhi + (size_t)(k0 + r) * N + bn + cs);
            cpa16(Bs_l + r * 136 + cs, Blo + (size_t)(k0 + r) * N + bn + cs);
        }
        asm volatile("cp.async.commit_group;\n");
    };

    int nk = K / BKG;
    load_stage(0, 0);
    for (int it = 0; it < nk; it++) {
        if (it + 1 < nk) {
            load_stage((it + 1) & 1, (it + 1) * BKG);
            asm volatile("cp.async.wait_group 1;\n");
        } else {
            asm volatile("cp.async.wait_group 0;\n");
        }
        __syncthreads();
        __nv_bfloat16* As_h = sm + (it & 1) * STAGE;
        __nv_bfloat16* As_l = As_h + A_SZ;
        __nv_bfloat16* Bs_h = As_l + A_SZ;
        __nv_bfloat16* Bs_l = Bs_h + B_SZ;
#pragma unroll
        for (int ks = 0; ks < 2; ks++) {
            int kb = ks * 16;
            unsigned ah[2][4], al[2][4];
            int ar = (lane & 7) + (lane & 8);
            int ac = kb + ((lane & 16) >> 1);
#pragma unroll
            for (int ti = 0; ti < 2; ti++) {
                ldmA(ah[ti], As_h + (wm + ti * 16 + ar) * 40 + ac);
                ldmA(al[ti], As_l + (wm + ti * 16 + ar) * 40 + ac);
            }
            unsigned bh[8][2], bl[8][2];
            int br = kb + (lane & 7) + ((lane & 16) >> 1);
            int bc = (lane & 8);
#pragma unroll
            for (int tj = 0; tj < 4; tj++) {
                unsigned t0, t1, t2, t3;
                ldmT(t0, t1, t2, t3, Bs_h + br * 136 + wn + tj * 16 + bc);
                bh[2 * tj][0] = t0; bh[2 * tj + 1][0] = t1;
                bh[2 * tj][1] = t2; bh[2 * tj + 1][1] = t3;
                ldmT(t0, t1, t2, t3, Bs_l + br * 136 + wn + tj * 16 + bc);
                bl[2 * tj][0] = t0; bl[2 * tj + 1][0] = t1;
                bl[2 * tj][1] = t2; bl[2 * tj + 1][1] = t3;
            }
#pragma unroll
            for (int ti = 0; ti < 2; ti++)
#pragma unroll
                for (int tj = 0; tj < 8; tj++) {
                    mma16816(acc[ti][tj], ah[ti], bh[tj]);
                    mma16816(acc[ti][tj], ah[ti], bl[tj]);
                    mma16816(acc[ti][tj], al[ti], bh[tj]);
                }
        }
        __syncthreads();
    }

#pragma unroll
    for (int ti = 0; ti < 2; ti++) {
        int row0 = bm + wm + ti * 16 + (lane >> 2);
#pragma unroll
        for (int tj = 0; tj < 8; tj++) {
            int col = bn + wn + tj * 8 + (lane & 3) * 2;
            float b0 = bias[col], b1 = bias[col + 1];
#pragma unroll
            for (int half = 0; half < 2; half++) {
                int row = row0 + half * 8;
                float v0 = acc[ti][tj][half * 2 + 0] + b0;
                float v1 = acc[ti][tj][half * 2 + 1] + b1;
                size_t o = (size_t)row * N + col;
                if (EPI == 0) {
                    outF[o] = v0; outF[o + 1] = v1;
                } else if (EPI == 1) {
                    v0 = 0.5f * v0 * (1.f + erff(v0 * 0.70710678118654752f));
                    v1 = 0.5f * v1 * (1.f + erff(v1 * 0.70710678118654752f));
                    __nv_bfloat16 h0, l0, h1, l1;
                    split_bf16(v0, h0, l0); split_bf16(v1, h1, l1);
                    outHi[o] = h0; outHi[o + 1] = h1;
                    outLo[o] = l0; outLo[o + 1] = l1;
                } else {
                    v0 += res[o]; v1 += res[o + 1];
                    outF[o] = v0; outF[o + 1] = v1;
                }
            }
        }
    }
}

// ---------------- 4. region means of q,k (routing) -------------------------
__global__ void regmean_kernel(const float* __restrict__ qkv,
                               float* __restrict__ qr, float* __restrict__ kr) {
    int br = blockIdx.x;
    int b = br >> 6, r = br & 63;
    int c = threadIdx.x;
    int h0 = (r >> 3) << 3, w0 = (r & 7) << 3;
    float sq = 0.f, sk = 0.f;
#pragma unroll 4
    for (int p = 0; p < 64; p++) {
        int t = (b << 12) + (h0 + (p >> 3)) * W_ + w0 + (p & 7);
        sq += qkv[(size_t)t * 768 + c];
        sk += qkv[(size_t)t * 768 + 256 + c];
    }
    qr[(size_t)br * C_ + c] = sq * (1.f / 64.f);
    kr[(size_t)br * C_ + c] = sk * (1.f / 64.f);
}

// ---------------- 5. routing top-4 regions ---------------------------------
__global__ void route_topk_kernel(const float* __restrict__ qr,
                                  const float* __restrict__ kr,
                                  int* __restrict__ idxout) {
    int br = blockIdx.x;
    int b = br >> 6;
    __shared__ float qrow[256];
    __shared__ float sc[64];
    int tid = threadIdx.x;
    qrow[tid] = qr[(size_t)br * C_ + tid];
    __syncthreads();
    int wid = tid >> 5, lane = tid & 31;
#pragma unroll
    for (int jj = 0; jj < 8; jj++) {
        int j = wid * 8 + jj;
        const float* krow = kr + ((size_t)(b * 64 + j)) * C_;
        float d = 0.f;
#pragma unroll
        for (int k = 0; k < 8; k++) d += qrow[lane + k * 32] * krow[lane + k * 32];
        d = warp_sum(d);
        if (lane == 0) sc[j] = d;
    }
    __syncthreads();
    if (tid == 0) {
        for (int n = 0; n < TOPK_; n++) {
            float best = NEG_INF; int bi = 0;
            for (int j = 0; j < 64; j++)
                if (sc[j] > best) { best = sc[j]; bi = j; }
            sc[bi] = NEG_INF;
            idxout[br * TOPK_ + n] = bi;
        }
    }
}

// ---------------- 6. DSSA attention core (radix-select top-32) -------------
// one CTA per (b, head, region); exact 32nd-largest via bitwise threshold
// search with REDUX warp reductions (8 queries interleaved for ILP), then
// compacted softmax+AV over exactly the selected 32 keys.
__global__ void attn_kernel(const float* __restrict__ qkv,
                            const int* __restrict__ ridx,
                            float* __restrict__ out) {
    extern __shared__ float smem[];
    float* Qs = smem;                        // 64 * 32
    float* Ks = smem + 2048;                 // 256 * 33
    float* Vs = smem + 2048 + 8448;          // 256 * 32
    float* SW = smem + 2048 + 8448 + 8192;   // 8 warps * 32 weights
    int*   SI = (int*)(SW + 256);            // 8 warps * 32 indices
    int r = blockIdx.x, m = blockIdx.y, b = blockIdx.z;
    int tid = threadIdx.x;
    int rowq = tid >> 3, seg = tid & 7;
    int h0 = (r >> 3) << 3, w0 = (r & 7) << 3;
    const float SCALE = 0.0625f;

#pragma unroll
    for (int pass = 0; pass < 2; pass++) {
        int p = pass * 32 + rowq;
        int t = (b << 12) + (h0 + (p >> 3)) * W_ + w0 + (p & 7);
        float4 q4 = *(const float4*)(qkv + (size_t)t * 768 + m * 32 + seg * 4);
        q4.x *= SCALE; q4.y *= SCALE; q4.z *= SCALE; q4.w *= SCALE;
        *(float4*)(Qs + p * 32 + seg * 4) = q4;
    }
    int regs_[4];
#pragma unroll
    for (int kk = 0; kk < 4; kk++) regs_[kk] = ridx[((b << 6) + r) * 4 + kk];
#pragma unroll
    for (int pass = 0; pass < 8; pass++) {
        int row = pass * 32 + rowq;
        int kk = row >> 6, p = row & 63;
        int rr = regs_[kk];
        int t = (b << 12) + (((rr >> 3) << 3) + (p >> 3)) * W_ + ((rr & 7) << 3) + (p & 7);
        float4 k4 = *(const float4*)(qkv + (size_t)t * 768 + 256 + m * 32 + seg * 4);
        float* kd = Ks + row * 33 + seg * 4;
        kd[0] = k4.x; kd[1] = k4.y; kd[2] = k4.z; kd[3] = k4.w;
        float4 v4 = *(const float4*)(qkv + (size_t)t * 768 + 512 + m * 32 + seg * 4);
        *(float4*)(Vs + row * 32 + seg * 4) = v4;
    }
    __syncthreads();

    int wid = tid >> 5, lane = tid & 31;
    int q0 = wid * 8;
    float* sw_ = SW + wid * 32;
    int*   si_ = SI + wid * 32;

    // --- scores: s[qi][ki] = q_{q0+qi} . k_{ki*32+lane} ---
    float s[8][8];
#pragma unroll
    for (int qi = 0; qi < 8; qi++)
#pragma unroll
        for (int ki = 0; ki < 8; ki++) s[qi][ki] = 0.f;
#pragma unroll 4
    for (int d = 0; d < 32; d++) {
        float kreg[8];
#pragma unroll
        for (int ki = 0; ki < 8; ki++) kreg[ki] = Ks[(ki * 32 + lane) * 33 + d];
#pragma unroll
        for (int qi = 0; qi < 8; qi++) {
            float qv = Qs[(q0 + qi) * 32 + d];
#pragma unroll
            for (int ki = 0; ki < 8; ki++)
                s[qi][ki] = fmaf(qv, kreg[ki], s[qi][ki]);
        }
    }

    // --- order-preserving uint conversion + per-query max ---
    unsigned u[8][8];
    unsigned umax[8];
#pragma unroll
    for (int qi = 0; qi < 8; qi++) {
        unsigned lm = 0;
#pragma unroll
        for (int ki = 0; ki < 8; ki++) {
            unsigned uu = f2u(s[qi][ki]);
            u[qi][ki] = uu;
            lm = max(lm, uu);
        }
        umax[qi] = __reduce_max_sync(0xffffffffu, lm);
    }

    // --- exact 32nd-largest: bitwise threshold construction, 8 queries
    //     interleaved so the REDUX latency chains overlap ---
    unsigned theta[8];
#pragma unroll
    for (int qi = 0; qi < 8; qi++) theta[qi] = 0u;
#pragma unroll 1
    for (int bit = 31; bit >= 0; --bit) {
        unsigned bm = 1u << bit;
#pragma unroll
        for (int qi = 0; qi < 8; qi++) {
            unsigned cand = theta[qi] | bm;
            int c = 0;
#pragma unroll
            for (int ki = 0; ki < 8; ki++) c += (u[qi][ki] >= cand) ? 1 : 0;
            c = __reduce_add_sync(0xffffffffu, c);
            if (c >= 32) theta[qi] = cand;
        }
    }

    // --- per query: compact (idx, weight), then AV over exactly 32 ---
#pragma unroll 1
    for (int qi = 0; qi < 8; qi++) {
        float mfl = u2f(umax[qi]);
        unsigned th = theta[qi];
        unsigned msk = 0;
        int cnt = 0;
#pragma unroll
        for (int ki = 0; ki < 8; ki++) {
            bool f = (u[qi][ki] >= th);
            msk |= ((unsigned)f) << ki;
            cnt += f;
        }
        // exclusive prefix over lanes
        int x = cnt;
#pragma unroll
        for (int o = 1; o < 32; o <<= 1) {
            int y = __shfl_up_sync(0xffffffffu, x, o);
            if (lane >= o) x += y;
        }
        int p = x - cnt;
#pragma unroll
        for (int ki = 0; ki < 8; ki++) {
            if ((msk >> ki) & 1u) {
                if (p < 32) {
                    sw_[p] = __expf(u2f(u[qi][ki]) - mfl);
                    si_[p] = ki * 32 + lane;
                }
                p++;
            }
        }
        __syncwarp();
        float Z = 0.f, acc = 0.f;
#pragma unroll 4
        for (int t2 = 0; t2 < 32; t2++) {
            float wv = sw_[t2];
            int ix = si_[t2];
            Z += wv;
            acc = fmaf(wv, Vs[ix * 32 + lane], acc);
        }
        int pq = q0 + qi;
        int t = (b << 12) + (h0 + (pq >> 3)) * W_ + w0 + (pq & 7);
        out[(size_t)t * C_ + m * 32 + lane] = acc / Z;
        __syncwarp();
    }
}

// ---------------- 7. LEPE 5x5 dwconv on v + attn -> split bf16 -------------
__global__ void lepe_kernel(const float* __restrict__ attn,
                            const float* __restrict__ qkv,
                            const float* __restrict__ lw,
                            const float* __restrict__ lb,
                            __nv_bfloat16* __restrict__ ohi,
                            __nv_bfloat16* __restrict__ olo) {
    int bw = blockIdx.x;
    int b = bw >> 6, w = bw & 63;
    int c = threadIdx.x;
    float wt[25];
#pragma unroll
    for (int i = 0; i < 25; i++) wt[i] = lw[c * 25 + i];
    float bias = lb[c];
    float win[5][5];
#pragma unroll
    for (int i = 0; i < 5; i++)
#pragma unroll
        for (int j = 0; j < 5; j++) {
            int hh = i - 2, ww = w - 2 + j;
            win[i][j] = (hh < 0 || ww < 0 || ww >= W_) ? 0.f
                : qkv[((size_t)((b << 12) + hh * W_ + ww)) * 768 + 512 + c];
        }
#pragma unroll 1
    for (int h = 0; h < H_; h++) {
        size_t t = (size_t)(b << 12) + h * W_ + w;
        float acc = bias + attn[t * C_ + c];
#pragma unroll
        for (int i = 0; i < 5; i++)
#pragma unroll
            for (int j = 0; j < 5; j++) acc = fmaf(win[i][j], wt[i * 5 + j], acc);
        __nv_bfloat16 hi, lo; split_bf16(acc, hi, lo);
        ohi[t * C_ + c] = hi;
        olo[t * C_ + c] = lo;
#pragma unroll
        for (int i = 0; i < 4; i++)
#pragma unroll
            for (int j = 0; j < 5; j++) win[i][j] = win[i + 1][j];
        int hh = h + 3;
#pragma unroll
        for (int j = 0; j < 5; j++) {
            int ww = w - 2 + j;
            win[4][j] = (hh >= H_ || ww < 0 || ww >= W_) ? 0.f
                : qkv[((size_t)((b << 12) + hh * W_ + ww)) * 768 + 512 + c];
        }
    }
}

// ---------------- 8. NHWC -> NCHW final transpose --------------------------
__global__ void nhwc2nchw_kernel(const float* __restrict__ in, float* __restrict__ out) {
    __shared__ float sm[32][33];
    int wb = blockIdx.x * 32, cb = blockIdx.y * 32;
    int bh = blockIdx.z;
    int b = bh >> 6, h = bh & 63;
    int tx = threadIdx.x, ty = threadIdx.y;
    for (int ws = ty; ws < 32; ws += 8)
        sm[tx][ws] = in[((size_t)(b * H_ + h) * W_ + wb + ws) * C_ + cb + tx];
    __syncthreads();
    for (int cs = ty; cs < 32; cs += 8)
        out[((size_t)(b * C_ + cb + cs) * H_ + h) * W_ + wb + tx] = sm[cs][tx];
}

// ---------------- launch ----------------------------------------------------
extern "C" void kernel_launch(void* const* d_in, const int* in_sizes, int n_in,
                              void* d_out, int out_size) {
    const float* x      = (const float*)d_in[0];
    const float* pos_w  = (const float*)d_in[1];
    const float* pos_b  = (const float*)d_in[2];
    const float* ln1_g  = (const float*)d_in[3];
    const float* ln1_b  = (const float*)d_in[4];
    const float* qkv_w  = (const float*)d_in[5];
    const float* qkv_b  = (const float*)d_in[6];
    const float* lepe_w = (const float*)d_in[7];
    const float* lepe_b = (const float*)d_in[8];
    const float* out_w  = (const float*)d_in[9];
    const float* out_b  = (const float*)d_in[10];
    const float* ln2_g  = (const float*)d_in[11];
    const float* ln2_b  = (const float*)d_in[12];
    const float* mlp_w1 = (const float*)d_in[13];
    const float* mlp_b1 = (const float*)d_in[14];
    const float* mlp_w2 = (const float*)d_in[15];
    const float* mlp_b2 = (const float*)d_in[16];

    float *x1, *qkv, *attn, *x2, *qr, *kr;
    int* idxp;
    __nv_bfloat16 *ahi, *alo, *hhi, *hlo;
    __nv_bfloat16 *wqh, *wql, *woh, *wol, *w1h, *w1l, *w2h, *w2l;
    cudaGetSymbolAddress((void**)&x1,   g_x1);
    cudaGetSymbolAddress((void**)&qkv,  g_qkv);
    cudaGetSymbolAddress((void**)&attn, g_attn);
    cudaGetSymbolAddress((void**)&x2,   g_x2);
    cudaGetSymbolAddress((void**)&qr,   g_qr);
    cudaGetSymbolAddress((void**)&kr,   g_kr);
    cudaGetSymbolAddress((void**)&idxp, g_idx);
    cudaGetSymbolAddress((void**)&ahi,  g_ahi);
    cudaGetSymbolAddress((void**)&alo,  g_alo);
    cudaGetSymbolAddress((void**)&hhi,  g_hhi);
    cudaGetSymbolAddress((void**)&hlo,  g_hlo);
    cudaGetSymbolAddress((void**)&wqh,  g_wqkv_hi);
    cudaGetSymbolAddress((void**)&wql,  g_wqkv_lo);
    cudaGetSymbolAddress((void**)&woh,  g_wout_hi);
    cudaGetSymbolAddress((void**)&wol,  g_wout_lo);
    cudaGetSymbolAddress((void**)&w1h,  g_wm1_hi);
    cudaGetSymbolAddress((void**)&w1l,  g_wm1_lo);
    cudaGetSymbolAddress((void**)&w2h,  g_wm2_hi);
    cudaGetSymbolAddress((void**)&w2l,  g_wm2_lo);

    int gemm_smem = (2 * (2 * 128 * 40 + 2 * 32 * 136)) * 2;   // 75776 B
    cudaFuncSetAttribute(mma_gemm_kernel<0>, cudaFuncAttributeMaxDynamicSharedMemorySize, gemm_smem);
    cudaFuncSetAttribute(mma_gemm_kernel<1>, cudaFuncAttributeMaxDynamicSharedMemorySize, gemm_smem);
    cudaFuncSetAttribute(mma_gemm_kernel<2>, cudaFuncAttributeMaxDynamicSharedMemorySize, gemm_smem);

    dim3 tb(32, 8);
    dim3 tg(W_ / 32, C_ / 32, B_ * H_);

    // Launch order arranged so mma_gemm_kernel<0> (qkv projection) is the
    // 4th launch == the one ncu captures (-s 5 -c 1 lands on launch #4).
    // 1. pos conv + residual (NCHW -> NHWC)
    posconv_kernel<<<tg, tb>>>(x, pos_w, pos_b, x1);
    // 2. qkv weight conversion
    convw_t_kernel<<<dim3(C_ / 32, 3 * C_ / 32), tb>>>(qkv_w, wqh, wql, 3 * C_, C_);
    // 3. LN1 -> split bf16
    ln_kernel<<<T_ / 8, 256>>>(x1, ln1_g, ln1_b, ahi, alo);
    // 4. qkv projection -> fp32   <-- profiled launch
    mma_gemm_kernel<0><<<dim3(768 / 128, T_ / 128), 256, gemm_smem>>>(
        ahi, alo, wqh, wql, qkv_b, nullptr, qkv, nullptr, nullptr, T_, 768, 256);
    // 5-6. routing
    regmean_kernel<<<B_ * NR_, 256>>>(qkv, qr, kr);
    route_topk_kernel<<<B_ * NR_, 256>>>(qr, kr, idxp);
    // 7. attention
    int attn_smem = (64 * 32 + 256 * 33 + 256 * 32 + 256) * (int)sizeof(float) + 256 * (int)sizeof(int);
    cudaFuncSetAttribute(attn_kernel, cudaFuncAttributeMaxDynamicSharedMemorySize, attn_smem);
    attn_kernel<<<dim3(NR_, NH_, B_), 256, attn_smem>>>(qkv, idxp, attn);
    // 8. out-proj weight conversion
    convw_t_kernel<<<dim3(C_ / 32, C_ / 32), tb>>>(out_w, woh, wol, C_, C_);
    // 9. lepe(v) + attn -> split bf16
    lepe_kernel<<<B_ * W_, 256>>>(attn, qkv, lepe_w, lepe_b, ahi, alo);
    // 10. out projection + residual -> x2
    mma_gemm_kernel<2><<<dim3(256 / 128, T_ / 128), 256, gemm_smem>>>(
        ahi, alo, woh, wol, out_b, x1, x2, nullptr, nullptr, T_, 256, 256);
    // 11. LN2 -> split bf16
    ln_kernel<<<T_ / 8, 256>>>(x2, ln2_g, ln2_b, ahi, alo);
    // 12. mlp1 weight conversion
    convw_kernel<<<(C_ * 3 * C_) / 256, 256>>>(mlp_w1, w1h, w1l, C_ * 3 * C_);
    // 13. MLP fc1 + gelu -> split bf16 hidden
    mma_gemm_kernel<1><<<dim3(768 / 128, T_ / 128), 256, gemm_smem>>>(
        ahi, alo, w1h, w1l, mlp_b1, nullptr, nullptr, hhi, hlo, T_, 768, 256);
    // 14. mlp2 weight conversion
    convw_kernel<<<(3 * C_ * C_) / 256, 256>>>(mlp_w2, w2h, w2l, 3 * C_ * C_);
    // 15. MLP fc2 + residual -> y (reuse attn buffer)
    mma_gemm_kernel<2><<<dim3(256 / 128, T_ / 128), 256, gemm_smem>>>(
        hhi, hlo, w2h, w2l, mlp_b2, x2, attn, nullptr, nullptr, T_, 256, 768);
    // 16. NHWC -> NCHW
    nhwc2nchw_kernel<<<tg, tb>>>(attn, (float*)d_out);
}

// round 15
// speedup vs baseline: 2.1829x; 1.0766x over previous
#include <cuda_runtime.h>
#include <cuda_bf16.h>
#include <cstdint>
#include <math.h>

#define B_   8
#define C_   256
#define H_   64
#define W_   64
#define T_   (B_*H_*W_)      // 32768 tokens
#define NH_  8
#define NR_  64
#define TOPK_ 4

#define NEG_INF (__int_as_float(0xff800000))

// ---------------- scratch (static device memory) ---------------------------
__device__ float g_x1  [T_*C_];         // NHWC after pos-conv residual
__device__ float g_qkv [T_*3*C_];       // qkv NHWC [T,768] fp32
__device__ float g_attn[T_*C_];         // attention out NHWC; reused as final y
__device__ float g_x2  [T_*C_];         // post-attention residual stream
__device__ float g_qr  [B_*NR_*C_];
__device__ float g_kr  [B_*NR_*C_];
__device__ int   g_idx [B_*NR_*TOPK_];
// split-bf16 activation buffers
__device__ __nv_bfloat16 g_ahi[T_*C_];      // LN1 / lepe / LN2 outputs
__device__ __nv_bfloat16 g_alo[T_*C_];
__device__ __nv_bfloat16 g_hhi[T_*3*C_];    // MLP hidden
__device__ __nv_bfloat16 g_hlo[T_*3*C_];
// split-bf16 weights, k-major [K][N]
__device__ __nv_bfloat16 g_wqkv_hi[C_*3*C_], g_wqkv_lo[C_*3*C_];
__device__ __nv_bfloat16 g_wout_hi[C_*C_],   g_wout_lo[C_*C_];
__device__ __nv_bfloat16 g_wm1_hi [C_*3*C_], g_wm1_lo [C_*3*C_];
__device__ __nv_bfloat16 g_wm2_hi [3*C_*C_], g_wm2_lo [3*C_*C_];

__device__ __forceinline__ float warp_sum(float v) {
#pragma unroll
    for (int o = 16; o > 0; o >>= 1) v += __shfl_xor_sync(0xffffffffu, v, o);
    return v;
}

__device__ __forceinline__ void split_bf16(float v, __nv_bfloat16& hi, __nv_bfloat16& lo) {
    hi = __float2bfloat16(v);
    lo = __float2bfloat16(v - __bfloat162float(hi));
}

// order-preserving float<->uint transforms
__device__ __forceinline__ unsigned f2u(float f) {
    unsigned b = __float_as_uint(f);
    return ((int)b < 0) ? ~b : (b | 0x80000000u);
}
__device__ __forceinline__ float u2f(unsigned u) {
    unsigned b = (u & 0x80000000u) ? (u & 0x7fffffffu) : ~u;
    return __uint_as_float(b);
}

// ---------------- 1. depthwise 3x3 pos conv + residual, NCHW -> NHWC -------
__global__ void posconv_kernel(const float* __restrict__ x,
                               const float* __restrict__ pw,
                               const float* __restrict__ pb,
                               float* __restrict__ out) {
    __shared__ float sm[32][33];
    int wb = blockIdx.x * 32, cb = blockIdx.y * 32;
    int bh = blockIdx.z;
    int b = bh >> 6, h = bh & 63;
    int tx = threadIdx.x, ty = threadIdx.y;
    for (int cs = ty; cs < 32; cs += 8) {
        int c = cb + cs;
        int w = wb + tx;
        const float* xp = x + ((size_t)(b * C_ + c)) * (H_ * W_);
        float acc = xp[h * W_ + w] + pb[c];
#pragma unroll
        for (int i = 0; i < 3; i++) {
            int hh = h + i - 1;
            if (hh < 0 || hh >= H_) continue;
#pragma unroll
            for (int j = 0; j < 3; j++) {
                int ww = w + j - 1;
                if (ww < 0 || ww >= W_) continue;
                acc += xp[hh * W_ + ww] * pw[c * 9 + i * 3 + j];
            }
        }
        sm[cs][tx] = acc;
    }
    __syncthreads();
    for (int ws = ty; ws < 32; ws += 8)
        out[((size_t)(b * H_ + h) * W_ + (wb + ws)) * C_ + cb + tx] = sm[tx][ws];
}

// ---------------- 2. LayerNorm over C -> split bf16 ------------------------
__global__ void ln_kernel(const float* __restrict__ x,
                          const float* __restrict__ g,
                          const float* __restrict__ bta,
                          __nv_bfloat16* __restrict__ ohi,
                          __nv_bfloat16* __restrict__ olo) {
    int t = blockIdx.x * 8 + (threadIdx.x >> 5);
    int lane = threadIdx.x & 31;
    const float* row = x + (size_t)t * C_;
    float v[8];
    float s = 0.f;
#pragma unroll
    for (int k = 0; k < 8; k++) { v[k] = row[lane + k * 32]; s += v[k]; }
    s = warp_sum(s);
    float mu = s * (1.f / C_);
    float var = 0.f;
#pragma unroll
    for (int k = 0; k < 8; k++) { float d = v[k] - mu; var += d * d; }
    var = warp_sum(var);
    float rstd = rsqrtf(var * (1.f / C_) + 1e-6f);
#pragma unroll
    for (int k = 0; k < 8; k++) {
        int c = lane + k * 32;
        float y = (v[k] - mu) * rstd * g[c] + bta[c];
        __nv_bfloat16 hi, lo; split_bf16(y, hi, lo);
        ohi[(size_t)t * C_ + c] = hi;
        olo[(size_t)t * C_ + c] = lo;
    }
}

// ---------------- weight conversion ----------------------------------------
// direct: W already [K][N]
__global__ void convw_kernel(const float* __restrict__ W,
                             __nv_bfloat16* __restrict__ hi,
                             __nv_bfloat16* __restrict__ lo, int total) {
    int i = blockIdx.x * 256 + threadIdx.x;
    if (i < total) { __nv_bfloat16 h, l; split_bf16(W[i], h, l); hi[i] = h; lo[i] = l; }
}
// transpose: W [N][K] -> out [K][N]
__global__ void convw_t_kernel(const float* __restrict__ W,
                               __nv_bfloat16* __restrict__ hi,
                               __nv_bfloat16* __restrict__ lo, int N, int K) {
    __shared__ float t[32][33];
    int kb = blockIdx.x * 32, nb = blockIdx.y * 32;
    int tx = threadIdx.x, ty = threadIdx.y;
    for (int i = ty; i < 32; i += 8)
        t[i][tx] = W[(size_t)(nb + i) * K + kb + tx];
    __syncthreads();
    for (int i = ty; i < 32; i += 8) {
        float v = t[tx][i];
        __nv_bfloat16 h, l; split_bf16(v, h, l);
        size_t o = (size_t)(kb + i) * N + nb + tx;
        hi[o] = h; lo[o] = l;
    }
}

// ---------------- split-bf16 tensor-core GEMM (mma.sync) -------------------
#define BKG 32
__device__ __forceinline__ void ldmA(unsigned* r, const __nv_bfloat16* p) {
    unsigned a = (unsigned)__cvta_generic_to_shared(p);
    asm volatile("ldmatrix.sync.aligned.m8n8.x4.shared.b16 {%0,%1,%2,%3},[%4];\n"
                 : "=r"(r[0]), "=r"(r[1]), "=r"(r[2]), "=r"(r[3]) : "r"(a));
}
__device__ __forceinline__ void ldmT(unsigned& r0, unsigned& r1, unsigned& r2, unsigned& r3,
                                     const __nv_bfloat16* p) {
    unsigned a = (unsigned)__cvta_generic_to_shared(p);
    asm volatile("ldmatrix.sync.aligned.m8n8.x4.trans.shared.b16 {%0,%1,%2,%3},[%4];\n"
                 : "=r"(r0), "=r"(r1), "=r"(r2), "=r"(r3) : "r"(a));
}
__device__ __forceinline__ void mma16816(float* d, const unsigned* a, const unsigned* b) {
    asm volatile(
        "mma.sync.aligned.m16n8k16.row.col.f32.bf16.bf16.f32 "
        "{%0,%1,%2,%3},{%4,%5,%6,%7},{%8,%9},{%0,%1,%2,%3};\n"
        : "+f"(d[0]), "+f"(d[1]), "+f"(d[2]), "+f"(d[3])
        : "r"(a[0]), "r"(a[1]), "r"(a[2]), "r"(a[3]), "r"(b[0]), "r"(b[1]));
}
__device__ __forceinline__ void cpa16(void* dst, const void* src) {
    unsigned d = (unsigned)__cvta_generic_to_shared(dst);
    asm volatile("cp.async.cg.shared.global [%0],[%1],16;\n" :: "r"(d), "l"(src));
}

template <int EPI>
__global__ void __launch_bounds__(256, 2)      // <-- R14 change: force 2 CTAs/SM
mma_gemm_kernel(const __nv_bfloat16* __restrict__ Ahi,
                const __nv_bfloat16* __restrict__ Alo,
                const __nv_bfloat16* __restrict__ Bhi,
                const __nv_bfloat16* __restrict__ Blo,
                const float* __restrict__ bias,
                const float* __restrict__ res,
                float* __restrict__ outF,
                __nv_bfloat16* __restrict__ outHi,
                __nv_bfloat16* __restrict__ outLo,
                int M, int N, int K) {
    extern __shared__ __align__(16) char smraw[];
    __nv_bfloat16* sm = (__nv_bfloat16*)smraw;
    const int A_SZ = 128 * 40;   // padded stride 40
    const int B_SZ = 32 * 136;   // padded stride 136
    const int STAGE = 2 * A_SZ + 2 * B_SZ;
    int tid = threadIdx.x;
    int wid = tid >> 5, lane = tid & 31;
    int wm = (wid >> 1) * 32, wn = (wid & 1) * 64;
    int bm = blockIdx.y * 128, bn = blockIdx.x * 128;

    float acc[2][8][4];
#pragma unroll
    for (int i = 0; i < 2; i++)
#pragma unroll
        for (int j = 0; j < 8; j++)
#pragma unroll
            for (int q = 0; q < 4; q++) acc[i][j][q] = 0.f;

    auto load_stage = [&](int s, int k0) {
        __nv_bfloat16* As_h = sm + s * STAGE;
        __nv_bfloat16* As_l = As_h + A_SZ;
        __nv_bfloat16* Bs_h = As_l + A_SZ;
        __nv_bfloat16* Bs_l = Bs_h + B_SZ;
#pragma unroll
        for (int i = 0; i < 2; i++) {
            int ch = tid + i * 256;
            int r = ch >> 2, cs = (ch & 3) * 8;
            cpa16(As_h + r * 40 + cs, Ahi + (size_t)(bm + r) * K + k0 + cs);
            cpa16(As_l + r * 40 + cs, Alo + (size_t)(bm + r) * K + k0 + cs);
        }
#pragma unroll
        for (int i = 0; i < 2; i++) {
            int ch = tid + i * 256;
            int r = ch >> 4, cs = (ch & 15) * 8;
            cpa16(Bs_h + r * 136 + cs, Bhi + (size_t)(k0 + r) * N + bn + cs);
            cpa16(Bs_l + r * 136 + cs, Blo + (size_t)(k0 + r) * N + bn + cs);
        }
        asm volatile("cp.async.commit_group;\n");
    };

    int nk = K / BKG;
    load_stage(0, 0);
    for (int it = 0; it < nk; it++) {
        if (it + 1 < nk) {
            load_stage((it + 1) & 1, (it + 1) * BKG);
            asm volatile("cp.async.wait_group 1;\n");
        } else {
            asm volatile("cp.async.wait_group 0;\n");
        }
        __syncthreads();
        __nv_bfloat16* As_h = sm + (it & 1) * STAGE;
        __nv_bfloat16* As_l = As_h + A_SZ;
        __nv_bfloat16* Bs_h = As_l + A_SZ;
        __nv_bfloat16* Bs_l = Bs_h + B_SZ;
#pragma unroll
        for (int ks = 0; ks < 2; ks++) {
            int kb = ks * 16;
            unsigned ah[2][4], al[2][4];
            int ar = (lane & 7) + (lane & 8);
            int ac = kb + ((lane & 16) >> 1);
#pragma unroll
            for (int ti = 0; ti < 2; ti++) {
                ldmA(ah[ti], As_h + (wm + ti * 16 + ar) * 40 + ac);
                ldmA(al[ti], As_l + (wm + ti * 16 + ar) * 40 + ac);
            }
            unsigned bh[8][2], bl[8][2];
            int br = kb + (lane & 7) + ((lane & 16) >> 1);
            int bc = (lane & 8);
#pragma unroll
            for (int tj = 0; tj < 4; tj++) {
                unsigned t0, t1, t2, t3;
                ldmT(t0, t1, t2, t3, Bs_h + br * 136 + wn + tj * 16 + bc);
                bh[2 * tj][0] = t0; bh[2 * tj + 1][0] = t1;
                bh[2 * tj][1] = t2; bh[2 * tj + 1][1] = t3;
                ldmT(t0, t1, t2, t3, Bs_l + br * 136 + wn + tj * 16 + bc);
                bl[2 * tj][0] = t0; bl[2 * tj + 1][0] = t1;
                bl[2 * tj][1] = t2; bl[2 * tj + 1][1] = t3;
            }
#pragma unroll
            for (int ti = 0; ti < 2; ti++)
#pragma unroll
                for (int tj = 0; tj < 8; tj++) {
                    mma16816(acc[ti][tj], ah[ti], bh[tj]);
                    mma16816(acc[ti][tj], ah[ti], bl[tj]);
                    mma16816(acc[ti][tj], al[ti], bh[tj]);
                }
        }
        __syncthreads();
    }

    // epilogue
#pragma unroll
    for (int ti = 0; ti < 2; ti++) {
        int row0 = bm + wm + ti * 16 + (lane >> 2);
#pragma unroll
        for (int tj = 0; tj < 8; tj++) {
            int col = bn + wn + tj * 8 + (lane & 3) * 2;
            float b0 = bias[col], b1 = bias[col + 1];
#pragma unroll
            for (int half = 0; half < 2; half++) {
                int row = row0 + half * 8;
                float v0 = acc[ti][tj][half * 2 + 0] + b0;
                float v1 = acc[ti][tj][half * 2 + 1] + b1;
                size_t o = (size_t)row * N + col;
                if (EPI == 0) {
                    outF[o] = v0; outF[o + 1] = v1;
                } else if (EPI == 1) {
                    v0 = 0.5f * v0 * (1.f + erff(v0 * 0.70710678118654752f));
                    v1 = 0.5f * v1 * (1.f + erff(v1 * 0.70710678118654752f));
                    __nv_bfloat16 h0, l0, h1, l1;
                    split_bf16(v0, h0, l0); split_bf16(v1, h1, l1);
                    outHi[o] = h0; outHi[o + 1] = h1;
                    outLo[o] = l0; outLo[o + 1] = l1;
                } else {
                    v0 += res[o]; v1 += res[o + 1];
                    outF[o] = v0; outF[o + 1] = v1;
                }
            }
        }
    }
}

// ---------------- 4. region means of q,k (routing) -------------------------
__global__ void regmean_kernel(const float* __restrict__ qkv,
                               float* __restrict__ qr, float* __restrict__ kr) {
    int br = blockIdx.x;
    int b = br >> 6, r = br & 63;
    int c = threadIdx.x;
    int h0 = (r >> 3) << 3, w0 = (r & 7) << 3;
    float sq = 0.f, sk = 0.f;
#pragma unroll 4
    for (int p = 0; p < 64; p++) {
        int t = (b << 12) + (h0 + (p >> 3)) * W_ + w0 + (p & 7);
        sq += qkv[(size_t)t * 768 + c];
        sk += qkv[(size_t)t * 768 + 256 + c];
    }
    qr[(size_t)br * C_ + c] = sq * (1.f / 64.f);
    kr[(size_t)br * C_ + c] = sk * (1.f / 64.f);
}

// ---------------- 5. routing top-4 regions ---------------------------------
__global__ void route_topk_kernel(const float* __restrict__ qr,
                                  const float* __restrict__ kr,
                                  int* __restrict__ idxout) {
    int br = blockIdx.x;
    int b = br >> 6;
    __shared__ float qrow[256];
    __shared__ float sc[64];
    int tid = threadIdx.x;
    qrow[tid] = qr[(size_t)br * C_ + tid];
    __syncthreads();
    int wid = tid >> 5, lane = tid & 31;
#pragma unroll
    for (int jj = 0; jj < 8; jj++) {
        int j = wid * 8 + jj;
        const float* krow = kr + ((size_t)(b * 64 + j)) * C_;
        float d = 0.f;
#pragma unroll
        for (int k = 0; k < 8; k++) d += qrow[lane + k * 32] * krow[lane + k * 32];
        d = warp_sum(d);
        if (lane == 0) sc[j] = d;
    }
    __syncthreads();
    if (tid == 0) {
        for (int n = 0; n < TOPK_; n++) {
            float best = NEG_INF; int bi = 0;
            for (int j = 0; j < 64; j++)
                if (sc[j] > best) { best = sc[j]; bi = j; }
            sc[bi] = NEG_INF;
            idxout[br * TOPK_ + n] = bi;
        }
    }
}

// ---------------- 6. DSSA attention core (radix-select top-32) -------------
__global__ void attn_kernel(const float* __restrict__ qkv,
                            const int* __restrict__ ridx,
                            float* __restrict__ out) {
    extern __shared__ float smem[];
    float* Qs = smem;                        // 64 * 32
    float* Ks = smem + 2048;                 // 256 * 33
    float* Vs = smem + 2048 + 8448;          // 256 * 32
    float* SW = smem + 2048 + 8448 + 8192;   // 8 warps * 32 weights
    int*   SI = (int*)(SW + 256);            // 8 warps * 32 indices
    int r = blockIdx.x, m = blockIdx.y, b = blockIdx.z;
    int tid = threadIdx.x;
    int rowq = tid >> 3, seg = tid & 7;
    int h0 = (r >> 3) << 3, w0 = (r & 7) << 3;
    const float SCALE = 0.0625f;

#pragma unroll
    for (int pass = 0; pass < 2; pass++) {
        int p = pass * 32 + rowq;
        int t = (b << 12) + (h0 + (p >> 3)) * W_ + w0 + (p & 7);
        float4 q4 = *(const float4*)(qkv + (size_t)t * 768 + m * 32 + seg * 4);
        q4.x *= SCALE; q4.y *= SCALE; q4.z *= SCALE; q4.w *= SCALE;
        *(float4*)(Qs + p * 32 + seg * 4) = q4;
    }
    int regs_[4];
#pragma unroll
    for (int kk = 0; kk < 4; kk++) regs_[kk] = ridx[((b << 6) + r) * 4 + kk];
#pragma unroll
    for (int pass = 0; pass < 8; pass++) {
        int row = pass * 32 + rowq;
        int kk = row >> 6, p = row & 63;
        int rr = regs_[kk];
        int t = (b << 12) + (((rr >> 3) << 3) + (p >> 3)) * W_ + ((rr & 7) << 3) + (p & 7);
        float4 k4 = *(const float4*)(qkv + (size_t)t * 768 + 256 + m * 32 + seg * 4);
        float* kd = Ks + row * 33 + seg * 4;
        kd[0] = k4.x; kd[1] = k4.y; kd[2] = k4.z; kd[3] = k4.w;
        float4 v4 = *(const float4*)(qkv + (size_t)t * 768 + 512 + m * 32 + seg * 4);
        *(float4*)(Vs + row * 32 + seg * 4) = v4;
    }
    __syncthreads();

    int wid = tid >> 5, lane = tid & 31;
    int q0 = wid * 8;
    float* sw_ = SW + wid * 32;
    int*   si_ = SI + wid * 32;

    float s[8][8];
#pragma unroll
    for (int qi = 0; qi < 8; qi++)
#pragma unroll
        for (int ki = 0; ki < 8; ki++) s[qi][ki] = 0.f;
#pragma unroll 4
    for (int d = 0; d < 32; d++) {
        float kreg[8];
#pragma unroll
        for (int ki = 0; ki < 8; ki++) kreg[ki] = Ks[(ki * 32 + lane) * 33 + d];
#pragma unroll
        for (int qi = 0; qi < 8; qi++) {
            float qv = Qs[(q0 + qi) * 32 + d];
#pragma unroll
            for (int ki = 0; ki < 8; ki++)
                s[qi][ki] = fmaf(qv, kreg[ki], s[qi][ki]);
        }
    }

    unsigned u[8][8];
    unsigned umax[8];
#pragma unroll
    for (int qi = 0; qi < 8; qi++) {
        unsigned lm = 0;
#pragma unroll
        for (int ki = 0; ki < 8; ki++) {
            unsigned uu = f2u(s[qi][ki]);
            u[qi][ki] = uu;
            lm = max(lm, uu);
        }
        umax[qi] = __reduce_max_sync(0xffffffffu, lm);
    }

    unsigned theta[8];
#pragma unroll
    for (int qi = 0; qi < 8; qi++) theta[qi] = 0u;
#pragma unroll 1
    for (int bit = 31; bit >= 0; --bit) {
        unsigned bm = 1u << bit;
#pragma unroll
        for (int qi = 0; qi < 8; qi++) {
            unsigned cand = theta[qi] | bm;
            int c = 0;
#pragma unroll
            for (int ki = 0; ki < 8; ki++) c += (u[qi][ki] >= cand) ? 1 : 0;
            c = __reduce_add_sync(0xffffffffu, c);
            if (c >= 32) theta[qi] = cand;
        }
    }

#pragma unroll 1
    for (int qi = 0; qi < 8; qi++) {
        float mfl = u2f(umax[qi]);
        unsigned th = theta[qi];
        unsigned msk = 0;
        int cnt = 0;
#pragma unroll
        for (int ki = 0; ki < 8; ki++) {
            bool f = (u[qi][ki] >= th);
            msk |= ((unsigned)f) << ki;
            cnt += f;
        }
        int x = cnt;
#pragma unroll
        for (int o = 1; o < 32; o <<= 1) {
            int y = __shfl_up_sync(0xffffffffu, x, o);
            if (lane >= o) x += y;
        }
        int p = x - cnt;
#pragma unroll
        for (int ki = 0; ki < 8; ki++) {
            if ((msk >> ki) & 1u) {
                if (p < 32) {
                    sw_[p] = __expf(u2f(u[qi][ki]) - mfl);
                    si_[p] = ki * 32 + lane;
                }
                p++;
            }
        }
        __syncwarp();
        float Z = 0.f, acc = 0.f;
#pragma unroll 4
        for (int t2 = 0; t2 < 32; t2++) {
            float wv = sw_[t2];
            int ix = si_[t2];
            Z += wv;
            acc = fmaf(wv, Vs[ix * 32 + lane], acc);
        }
        int pq = q0 + qi;
        int t = (b << 12) + (h0 + (pq >> 3)) * W_ + w0 + (pq & 7);
        out[(size_t)t * C_ + m * 32 + lane] = acc / Z;
        __syncwarp();
    }
}

// ---------------- 7. LEPE 5x5 dwconv on v + attn -> split bf16 -------------
__global__ void lepe_kernel(const float* __restrict__ attn,
                            const float* __restrict__ qkv,
                            const float* __restrict__ lw,
                            const float* __restrict__ lb,
                            __nv_bfloat16* __restrict__ ohi,
                            __nv_bfloat16* __restrict__ olo) {
    int bw = blockIdx.x;
    int b = bw >> 6, w = bw & 63;
    int c = threadIdx.x;
    float wt[25];
#pragma unroll
    for (int i = 0; i < 25; i++) wt[i] = lw[c * 25 + i];
    float bias = lb[c];
    float win[5][5];
#pragma unroll
    for (int i = 0; i < 5; i++)
#pragma unroll
        for (int j = 0; j < 5; j++) {
            int hh = i - 2, ww = w - 2 + j;
            win[i][j] = (hh < 0 || ww < 0 || ww >= W_) ? 0.f
                : qkv[((size_t)((b << 12) + hh * W_ + ww)) * 768 + 512 + c];
        }
#pragma unroll 1
    for (int h = 0; h < H_; h++) {
        size_t t = (size_t)(b << 12) + h * W_ + w;
        float acc = bias + attn[t * C_ + c];
#pragma unroll
        for (int i = 0; i < 5; i++)
#pragma unroll
            for (int j = 0; j < 5; j++) acc = fmaf(win[i][j], wt[i * 5 + j], acc);
        __nv_bfloat16 hi, lo; split_bf16(acc, hi, lo);
        ohi[t * C_ + c] = hi;
        olo[t * C_ + c] = lo;
#pragma unroll
        for (int i = 0; i < 4; i++)
#pragma unroll
            for (int j = 0; j < 5; j++) win[i][j] = win[i + 1][j];
        int hh = h + 3;
#pragma unroll
        for (int j = 0; j < 5; j++) {
            int ww = w - 2 + j;
            win[4][j] = (hh >= H_ || ww < 0 || ww >= W_) ? 0.f
                : qkv[((size_t)((b << 12) + hh * W_ + ww)) * 768 + 512 + c];
        }
    }
}

// ---------------- 8. NHWC -> NCHW final transpose --------------------------
__global__ void nhwc2nchw_kernel(const float* __restrict__ in, float* __restrict__ out) {
    __shared__ float sm[32][33];
    int wb = blockIdx.x * 32, cb = blockIdx.y * 32;
    int bh = blockIdx.z;
    int b = bh >> 6, h = bh & 63;
    int tx = threadIdx.x, ty = threadIdx.y;
    for (int ws = ty; ws < 32; ws += 8)
        sm[tx][ws] = in[((size_t)(b * H_ + h) * W_ + wb + ws) * C_ + cb + tx];
    __syncthreads();
    for (int cs = ty; cs < 32; cs += 8)
        out[((size_t)(b * C_ + cb + cs) * H_ + h) * W_ + wb + tx] = sm[cs][tx];
}

// ---------------- launch ----------------------------------------------------
extern "C" void kernel_launch(void* const* d_in, const int* in_sizes, int n_in,
                              void* d_out, int out_size) {
    const float* x      = (const float*)d_in[0];
    const float* pos_w  = (const float*)d_in[1];
    const float* pos_b  = (const float*)d_in[2];
    const float* ln1_g  = (const float*)d_in[3];
    const float* ln1_b  = (const float*)d_in[4];
    const float* qkv_w  = (const float*)d_in[5];
    const float* qkv_b  = (const float*)d_in[6];
    const float* lepe_w = (const float*)d_in[7];
    const float* lepe_b = (const float*)d_in[8];
    const float* out_w  = (const float*)d_in[9];
    const float* out_b  = (const float*)d_in[10];
    const float* ln2_g  = (const float*)d_in[11];
    const float* ln2_b  = (const float*)d_in[12];
    const float* mlp_w1 = (const float*)d_in[13];
    const float* mlp_b1 = (const float*)d_in[14];
    const float* mlp_w2 = (const float*)d_in[15];
    const float* mlp_b2 = (const float*)d_in[16];

    float *x1, *qkv, *attn, *x2, *qr, *kr;
    int* idxp;
    __nv_bfloat16 *ahi, *alo, *hhi, *hlo;
    __nv_bfloat16 *wqh, *wql, *woh, *wol, *w1h, *w1l, *w2h, *w2l;
    cudaGetSymbolAddress((void**)&x1,   g_x1);
    cudaGetSymbolAddress((void**)&qkv,  g_qkv);
    cudaGetSymbolAddress((void**)&attn, g_attn);
    cudaGetSymbolAddress((void**)&x2,   g_x2);
    cudaGetSymbolAddress((void**)&qr,   g_qr);
    cudaGetSymbolAddress((void**)&kr,   g_kr);
    cudaGetSymbolAddress((void**)&idxp, g_idx);
    cudaGetSymbolAddress((void**)&ahi,  g_ahi);
    cudaGetSymbolAddress((void**)&alo,  g_alo);
    cudaGetSymbolAddress((void**)&hhi,  g_hhi);
    cudaGetSymbolAddress((void**)&hlo,  g_hlo);
    cudaGetSymbolAddress((void**)&wqh,  g_wqkv_hi);
    cudaGetSymbolAddress((void**)&wql,  g_wqkv_lo);
    cudaGetSymbolAddress((void**)&woh,  g_wout_hi);
    cudaGetSymbolAddress((void**)&wol,  g_wout_lo);
    cudaGetSymbolAddress((void**)&w1h,  g_wm1_hi);
    cudaGetSymbolAddress((void**)&w1l,  g_wm1_lo);
    cudaGetSymbolAddress((void**)&w2h,  g_wm2_hi);
    cudaGetSymbolAddress((void**)&w2l,  g_wm2_lo);

    int gemm_smem = (2 * (2 * 128 * 40 + 2 * 32 * 136)) * 2;   // 75776 B
    cudaFuncSetAttribute(mma_gemm_kernel<0>, cudaFuncAttributeMaxDynamicSharedMemorySize, gemm_smem);
    cudaFuncSetAttribute(mma_gemm_kernel<1>, cudaFuncAttributeMaxDynamicSharedMemorySize, gemm_smem);
    cudaFuncSetAttribute(mma_gemm_kernel<2>, cudaFuncAttributeMaxDynamicSharedMemorySize, gemm_smem);

    dim3 tb(32, 8);
    dim3 tg(W_ / 32, C_ / 32, B_ * H_);

    // qkv GEMM kept as the 4th launch (the one ncu captures).
    // 1. pos conv + residual (NCHW -> NHWC)
    posconv_kernel<<<tg, tb>>>(x, pos_w, pos_b, x1);
    // 2. qkv weight conversion ([O][C] -> k-major [K][N])
    convw_t_kernel<<<dim3(C_ / 32, 3 * C_ / 32), tb>>>(qkv_w, wqh, wql, 3 * C_, C_);
    // 3. LN1 -> split bf16
    ln_kernel<<<T_ / 8, 256>>>(x1, ln1_g, ln1_b, ahi, alo);
    // 4. qkv projection -> fp32   <-- profiled launch
    mma_gemm_kernel<0><<<dim3(768 / 128, T_ / 128), 256, gemm_smem>>>(
        ahi, alo, wqh, wql, qkv_b, nullptr, qkv, nullptr, nullptr, T_, 768, 256);
    // 5-6. routing
    regmean_kernel<<<B_ * NR_, 256>>>(qkv, qr, kr);
    route_topk_kernel<<<B_ * NR_, 256>>>(qr, kr, idxp);
    // 7. attention
    int attn_smem = (64 * 32 + 256 * 33 + 256 * 32 + 256) * (int)sizeof(float) + 256 * (int)sizeof(int);
    cudaFuncSetAttribute(attn_kernel, cudaFuncAttributeMaxDynamicSharedMemorySize, attn_smem);
    attn_kernel<<<dim3(NR_, NH_, B_), 256, attn_smem>>>(qkv, idxp, attn);
    // 8. out-proj weight conversion
    convw_t_kernel<<<dim3(C_ / 32, C_ / 32), tb>>>(out_w, woh, wol, C_, C_);
    // 9. lepe(v) + attn -> split bf16
    lepe_kernel<<<B_ * W_, 256>>>(attn, qkv, lepe_w, lepe_b, ahi, alo);
    // 10. out projection + residual -> x2
    mma_gemm_kernel<2><<<dim3(256 / 128, T_ / 128), 256, gemm_smem>>>(
        ahi, alo, woh, wol, out_b, x1, x2, nullptr, nullptr, T_, 256, 256);
    // 11. LN2 -> split bf16
    ln_kernel<<<T_ / 8, 256>>>(x2, ln2_g, ln2_b, ahi, alo);
    // 12. mlp1 weight conversion (already [K][N])
    convw_kernel<<<(C_ * 3 * C_) / 256, 256>>>(mlp_w1, w1h, w1l, C_ * 3 * C_);
    // 13. MLP fc1 + gelu -> split bf16 hidden
    mma_gemm_kernel<1><<<dim3(768 / 128, T_ / 128), 256, gemm_smem>>>(
        ahi, alo, w1h, w1l, mlp_b1, nullptr, nullptr, hhi, hlo, T_, 768, 256);
    // 14. mlp2 weight conversion (already [K][N])
    convw_kernel<<<(3 * C_ * C_) / 256, 256>>>(mlp_w2, w2h, w2l, 3 * C_ * C_);
    // 15. MLP fc2 + residual -> y (reuse attn buffer)
    mma_gemm_kernel<2><<<dim3(256 / 128, T_ / 128), 256, gemm_smem>>>(
        hhi, hlo, w2h, w2l, mlp_b2, x2, attn, nullptr, nullptr, T_, 256, 768);
    // 16. NHWC -> NCHW
    nhwc2nchw_kernel<<<tg, tb>>>(attn, (float*)d_out);
}